// round 1
// baseline (speedup 1.0000x reference)
#include <cuda_runtime.h>
#include <math.h>

#define BATCH 2
#define SEQ   2048
#define EMB   1024
#define HEADS 16
#define HDIM  64
#define NPAIR 32   // HDIM/2
#define MROWS (BATCH*SEQ)   // 4096

// ---------------- scratch (device globals; no allocation allowed) ----------------
__device__ float g_q[BATCH*HEADS*SEQ*HDIM];
__device__ float g_k[BATCH*HEADS*SEQ*HDIM];
__device__ float g_v[BATCH*HEADS*SEQ*HDIM];
__device__ float g_gate[BATCH*SEQ*EMB];
__device__ float g_hidden[BATCH*SEQ*EMB];
__device__ float g_sin[SEQ*NPAIR];
__device__ float g_cos[SEQ*NPAIR];
__device__ float g_gpow[HEADS*SEQ];

// ---------------- table init (RoPE sin/cos, decay powers) ----------------
__global__ void init_tables() {
    int tid = blockIdx.x * blockDim.x + threadIdx.x;
    if (tid < SEQ * NPAIR) {
        int n = tid / NPAIR, p = tid % NPAIR;
        float x = (float)p / 31.0f;
        float theta = (float)exp(-(double)x * 9.210340371976184);  // ln(10000)
        float ang = (float)n * theta;   // fp32 round to match reference
        g_sin[tid] = (float)sin((double)ang);
        g_cos[tid] = (float)cos((double)ang);
    }
    if (tid < HEADS * SEQ) {
        int h = tid / SEQ, dist = tid % SEQ;
        double t = (double)h / 15.0;
        float l = (float)((1.0 - t) * (-3.4657359027997265) + t * (-6.238324625039508));
        float gamma = 1.0f - expf(l);
        g_gpow[tid] = (float)exp((double)dist * log((double)gamma));
    }
}

// ---------------- NT SGEMM: C[m][j] = sum_k A[m][k] * W[j][k] + b[j] ----------------
// A: [4096 x 1024] row-major, W: [1024 x 1024] row-major. 128x128x8 tile, 8x8/thread.
// MODE 0: plain, (B,N,E) out       MODE 1: RoPE, (B,H,N,D) out
// MODE 2: RoPE*0.125, (B,H,N,D)    MODE 3: plain, (B,H,N,D)
// MODE 4: SiLU, (B,N,E)
template<int MODE>
__global__ __launch_bounds__(256) void gemm_nt(const float* __restrict__ A,
                                               const float* __restrict__ W,
                                               const float* __restrict__ bias,
                                               float* __restrict__ C) {
    __shared__ float As[8][128];
    __shared__ float Ws[8][128];
    const int tid = threadIdx.x;
    const int m0 = blockIdx.y * 128;
    const int j0 = blockIdx.x * 128;
    const int tx = tid % 16, ty = tid / 16;

    const int arow = tid >> 1;
    const int acol4 = (tid & 1) * 4;
    const float* Ap = A + (size_t)(m0 + arow) * EMB + acol4;
    const float* Wp = W + (size_t)(j0 + arow) * EMB + acol4;

    float acc[8][8];
#pragma unroll
    for (int i = 0; i < 8; ++i)
#pragma unroll
        for (int j = 0; j < 8; ++j) acc[i][j] = 0.f;

    float4 av = *(const float4*)Ap;
    float4 wv = *(const float4*)Wp;

    for (int k0 = 0; k0 < EMB; k0 += 8) {
        As[acol4 + 0][arow] = av.x; As[acol4 + 1][arow] = av.y;
        As[acol4 + 2][arow] = av.z; As[acol4 + 3][arow] = av.w;
        Ws[acol4 + 0][arow] = wv.x; Ws[acol4 + 1][arow] = wv.y;
        Ws[acol4 + 2][arow] = wv.z; Ws[acol4 + 3][arow] = wv.w;
        __syncthreads();
        if (k0 + 8 < EMB) {
            av = *(const float4*)(Ap + k0 + 8);
            wv = *(const float4*)(Wp + k0 + 8);
        }
#pragma unroll
        for (int k = 0; k < 8; ++k) {
            float a[8], b[8];
            *(float4*)&a[0] = *(const float4*)&As[k][ty * 4];
            *(float4*)&a[4] = *(const float4*)&As[k][64 + ty * 4];
            *(float4*)&b[0] = *(const float4*)&Ws[k][tx * 4];
            *(float4*)&b[4] = *(const float4*)&Ws[k][64 + tx * 4];
#pragma unroll
            for (int i = 0; i < 8; ++i)
#pragma unroll
                for (int j = 0; j < 8; ++j) acc[i][j] += a[i] * b[j];
        }
        __syncthreads();
    }

    // bias per column (8 cols per thread)
    float brow[8];
#pragma unroll
    for (int jj = 0; jj < 8; ++jj) {
        int c = j0 + ((jj < 4) ? (tx * 4 + jj) : (64 + tx * 4 + jj - 4));
        brow[jj] = bias[c];
    }

#pragma unroll
    for (int ii = 0; ii < 8; ++ii) {
        int r = (ii < 4) ? (ty * 4 + ii) : (64 + ty * 4 + ii - 4);
        int m = m0 + r;
        int bb = m >> 11;           // / SEQ
        int n = m & (SEQ - 1);
#pragma unroll
        for (int jg = 0; jg < 2; ++jg) {
            int cbase = j0 + jg * 64 + tx * 4;
            float v0 = acc[ii][jg * 4 + 0] + brow[jg * 4 + 0];
            float v1 = acc[ii][jg * 4 + 1] + brow[jg * 4 + 1];
            float v2 = acc[ii][jg * 4 + 2] + brow[jg * 4 + 2];
            float v3 = acc[ii][jg * 4 + 3] + brow[jg * 4 + 3];
            if (MODE == 1 || MODE == 2) {
                int p0 = (cbase & 63) >> 1;      // pair index (even)
                float s0 = g_sin[n * NPAIR + p0],     c0 = g_cos[n * NPAIR + p0];
                float s1 = g_sin[n * NPAIR + p0 + 1], c1 = g_cos[n * NPAIR + p0 + 1];
                float t0 = v0 * c0 - v1 * s0;
                float t1 = v1 * c0 + v0 * s0;
                float t2 = v2 * c1 - v3 * s1;
                float t3 = v3 * c1 + v2 * s1;
                v0 = t0; v1 = t1; v2 = t2; v3 = t3;
                if (MODE == 2) { v0 *= 0.125f; v1 *= 0.125f; v2 *= 0.125f; v3 *= 0.125f; }
            }
            if (MODE == 4) {
                v0 = v0 / (1.f + expf(-v0));
                v1 = v1 / (1.f + expf(-v1));
                v2 = v2 / (1.f + expf(-v2));
                v3 = v3 / (1.f + expf(-v3));
            }
            float4 val = make_float4(v0, v1, v2, v3);
            if (MODE == 0 || MODE == 4) {
                *(float4*)&C[(size_t)(bb * SEQ + n) * EMB + cbase] = val;
            } else {
                int h = cbase >> 6, d = cbase & 63;
                *(float4*)&C[((size_t)((bb * HEADS + h) * SEQ + n)) * HDIM + d] = val;
            }
        }
    }
}

// ---------------- retention attention ----------------
// grid (32 qtiles, H, B), 256 threads. Flash-style loop over causal key tiles.
// Decay via gamma^dist table; groupnorm + gate fused into epilogue.
#define ATP 68                       // smem pitch (floats), %4==0 for float4 alignment
#define AT_SMEM_FLOATS (4*64*ATP + SEQ + 128)
#define AT_SMEM_BYTES  (AT_SMEM_FLOATS*4)

__global__ __launch_bounds__(256) void attention_kernel() {
    extern __shared__ float sm[];
    float* qs = sm;                       // [64][ATP] q tile, row-major [i][d]
    float* ks = sm + 64 * ATP;            // [64][ATP] k tile  [j][d]
    float* vs = sm + 2 * 64 * ATP;        // [64][ATP] v tile  [j][d]
    float* ss = sm + 3 * 64 * ATP;        // [64][ATP] S tile [i][j]; reused as O [i][d]
    float* gp = sm + 4 * 64 * ATP;        // [2048] gamma^dist
    float* mu = gp + SEQ;                 // [64]
    float* rs = mu + 64;                  // [64]

    const int tid = threadIdx.x;
    const int qt = blockIdx.x, h = blockIdx.y, b = blockIdx.z;
    const int q0 = qt * 64;
    const size_t headbase = (size_t)(b * HEADS + h) * SEQ * HDIM;
    const float* qg = g_q + headbase;
    const float* kg = g_k + headbase;
    const float* vg = g_v + headbase;

    for (int i = tid; i < SEQ; i += 256) gp[i] = g_gpow[h * SEQ + i];
    for (int f = tid; f < 1024; f += 256) {
        int row = f >> 4, d4 = (f & 15) * 4;
        *(float4*)&qs[row * ATP + d4] = *(const float4*)&qg[(size_t)(q0 + row) * HDIM + d4];
    }

    const int tx = tid % 16, ty = tid / 16;
    float oacc[4][4];
#pragma unroll
    for (int i = 0; i < 4; ++i)
#pragma unroll
        for (int j = 0; j < 4; ++j) oacc[i][j] = 0.f;

    for (int kt = 0; kt <= qt; ++kt) {
        const int k0 = kt * 64;
        __syncthreads();   // protect ks/vs/ss from previous iteration's readers
        for (int f = tid; f < 1024; f += 256) {
            int row = f >> 4, d4 = (f & 15) * 4;
            *(float4*)&ks[row * ATP + d4] = *(const float4*)&kg[(size_t)(k0 + row) * HDIM + d4];
            *(float4*)&vs[row * ATP + d4] = *(const float4*)&vg[(size_t)(k0 + row) * HDIM + d4];
        }
        __syncthreads();

        // S[i][j] = sum_d q[i][d]*k[j][d]; i = ty+16*ii, j = tx+16*jj
        float sacc[4][4];
#pragma unroll
        for (int i = 0; i < 4; ++i)
#pragma unroll
            for (int j = 0; j < 4; ++j) sacc[i][j] = 0.f;

#pragma unroll
        for (int d4 = 0; d4 < 64; d4 += 4) {
            float4 qa[4], kb[4];
#pragma unroll
            for (int u = 0; u < 4; ++u) qa[u] = *(const float4*)&qs[(ty + 16 * u) * ATP + d4];
#pragma unroll
            for (int u = 0; u < 4; ++u) kb[u] = *(const float4*)&ks[(tx + 16 * u) * ATP + d4];
#pragma unroll
            for (int i = 0; i < 4; ++i)
#pragma unroll
                for (int j = 0; j < 4; ++j) {
                    sacc[i][j] += qa[i].x * kb[j].x;
                    sacc[i][j] += qa[i].y * kb[j].y;
                    sacc[i][j] += qa[i].z * kb[j].z;
                    sacc[i][j] += qa[i].w * kb[j].w;
                }
        }

        // apply decay + causal (idx >= 0 is exactly the causal condition)
        const int dist0 = (qt - kt) * 64;
#pragma unroll
        for (int i = 0; i < 4; ++i) {
            int gi = ty + 16 * i;
#pragma unroll
            for (int j = 0; j < 4; ++j) {
                int gj = tx + 16 * j;
                int idx = dist0 + gi - gj;
                float w = (idx >= 0) ? gp[idx] : 0.f;
                ss[gi * ATP + gj] = sacc[i][j] * w;
            }
        }
        __syncthreads();

        // O[i][d] += sum_j S[i][j] * v[j][d]; d = tx+16*jj
#pragma unroll 4
        for (int j = 0; j < 64; ++j) {
            float sa[4], vb[4];
#pragma unroll
            for (int u = 0; u < 4; ++u) sa[u] = ss[(ty + 16 * u) * ATP + j];
#pragma unroll
            for (int u = 0; u < 4; ++u) vb[u] = vs[j * ATP + tx + 16 * u];
#pragma unroll
            for (int i = 0; i < 4; ++i)
#pragma unroll
                for (int jj = 0; jj < 4; ++jj) oacc[i][jj] += sa[i] * vb[jj];
        }
    }
    __syncthreads();

    // write O into ss as [i][d]
#pragma unroll
    for (int i = 0; i < 4; ++i)
#pragma unroll
        for (int jj = 0; jj < 4; ++jj)
            ss[(ty + 16 * i) * ATP + tx + 16 * jj] = oacc[i][jj];
    __syncthreads();

    // groupnorm stats per row (two-pass)
    if (tid < 64) {
        float s = 0.f;
        for (int d = 0; d < 64; ++d) s += ss[tid * ATP + d];
        float m = s * (1.f / 64.f);
        float vv = 0.f;
        for (int d = 0; d < 64; ++d) { float dd = ss[tid * ATP + d] - m; vv += dd * dd; }
        vv *= (1.f / 64.f);
        mu[tid] = m;
        rs[tid] = rsqrtf(vv + 1e-6f);
    }
    __syncthreads();

    // normalize, multiply by gate, write hidden (B,N,E)
    for (int f = tid; f < 4096; f += 256) {
        int i = f >> 6, d = f & 63;
        int n = q0 + i;
        float val = (ss[i * ATP + d] - mu[i]) * rs[i];
        size_t eidx = (size_t)(b * SEQ + n) * EMB + h * HDIM + d;
        g_hidden[eidx] = val * g_gate[eidx];
    }
}

// ---------------- launch ----------------
extern "C" void kernel_launch(void* const* d_in, const int* in_sizes, int n_in,
                              void* d_out, int out_size) {
    const float* query  = (const float*)d_in[0];
    const float* key_in = (const float*)d_in[1];
    const float* value  = (const float*)d_in[2];
    const float* Wq = (const float*)d_in[3];
    const float* bq = (const float*)d_in[4];
    const float* Wk = (const float*)d_in[5];
    const float* bk = (const float*)d_in[6];
    const float* Wv = (const float*)d_in[7];
    const float* bv = (const float*)d_in[8];
    const float* Wg = (const float*)d_in[9];
    const float* bg = (const float*)d_in[10];
    const float* Wo = (const float*)d_in[11];
    const float* bo = (const float*)d_in[12];
    float* out = (float*)d_out;

    float *qp, *kp, *vp, *gatep, *hidp;
    cudaGetSymbolAddress((void**)&qp, g_q);
    cudaGetSymbolAddress((void**)&kp, g_k);
    cudaGetSymbolAddress((void**)&vp, g_v);
    cudaGetSymbolAddress((void**)&gatep, g_gate);
    cudaGetSymbolAddress((void**)&hidp, g_hidden);

    cudaFuncSetAttribute(attention_kernel,
                         cudaFuncAttributeMaxDynamicSharedMemorySize, AT_SMEM_BYTES);

    init_tables<<<256, 256>>>();

    dim3 gg(EMB / 128, MROWS / 128);   // (8, 32)
    gemm_nt<1><<<gg, 256>>>(query,  Wq, bq, qp);     // q proj + RoPE -> BHND
    gemm_nt<2><<<gg, 256>>>(key_in, Wk, bk, kp);     // k proj + RoPE + 1/8 -> BHND
    gemm_nt<3><<<gg, 256>>>(value,  Wv, bv, vp);     // v proj -> BHND
    gemm_nt<4><<<gg, 256>>>(query,  Wg, bg, gatep);  // gate proj + SiLU -> BNE

    attention_kernel<<<dim3(SEQ / 64, HEADS, BATCH), 256, AT_SMEM_BYTES>>>();

    gemm_nt<0><<<gg, 256>>>(hidp, Wo, bo, out);      // output proj
}

// round 4
// speedup vs baseline: 2.0945x; 2.0945x over previous
#include <cuda_runtime.h>
#include <cuda_bf16.h>
#include <math.h>
#include <stdint.h>

#define BATCH 2
#define SEQ   2048
#define EMB   1024
#define HEADS 16
#define HDIM  64
#define NPAIR 32
#define MROWS (BATCH*SEQ)   // 4096

typedef __nv_bfloat16 bf16;

// ---------------- scratch (device globals; no allocation allowed) ----------------
__device__ float g_gate[BATCH*SEQ*EMB];
__device__ float g_sin[SEQ*NPAIR];
__device__ float g_cos[SEQ*NPAIR];
__device__ float g_gpow[HEADS*SEQ];

// bf16 hi/lo operands (16B aligned for vector epilogue stores)
__device__ __align__(16) bf16 g_xqh[MROWS*EMB], g_xql[MROWS*EMB];
__device__ __align__(16) bf16 g_xkh[MROWS*EMB], g_xkl[MROWS*EMB];
__device__ __align__(16) bf16 g_xvh[MROWS*EMB], g_xvl[MROWS*EMB];
__device__ __align__(16) bf16 g_hh [MROWS*EMB], g_hl [MROWS*EMB];
__device__ __align__(16) bf16 g_wqh[EMB*EMB], g_wql[EMB*EMB];
__device__ __align__(16) bf16 g_wkh[EMB*EMB], g_wkl[EMB*EMB];
__device__ __align__(16) bf16 g_wvh[EMB*EMB], g_wvl[EMB*EMB];
__device__ __align__(16) bf16 g_wgh[EMB*EMB], g_wgl[EMB*EMB];
__device__ __align__(16) bf16 g_woh[EMB*EMB], g_wol[EMB*EMB];
// projected q/k/v in [b][h][n][d], bf16 hi/lo
__device__ __align__(16) bf16 g_qh[MROWS*EMB], g_ql[MROWS*EMB];
__device__ __align__(16) bf16 g_kh[MROWS*EMB], g_kl[MROWS*EMB];
__device__ __align__(16) bf16 g_vh[MROWS*EMB], g_vl[MROWS*EMB];

// ---------------- helpers ----------------
__device__ __forceinline__ uint32_t smem_u32(const void* p) {
    uint32_t a;
    asm("{ .reg .u64 t; cvta.to.shared.u64 t, %1; cvt.u32.u64 %0, t; }" : "=r"(a) : "l"(p));
    return a;
}
__device__ __forceinline__ void cp16(uint32_t dst, const void* src) {
    asm volatile("cp.async.cg.shared.global [%0], [%1], 16;" :: "r"(dst), "l"(src));
}
#define CP_COMMIT() asm volatile("cp.async.commit_group;" ::: "memory")
#define CP_WAIT0()  asm volatile("cp.async.wait_group 0;" ::: "memory")
#define CP_WAIT1()  asm volatile("cp.async.wait_group 1;" ::: "memory")

__device__ __forceinline__ void ldsm4(uint32_t* r, uint32_t addr) {
    asm volatile("ldmatrix.sync.aligned.m8n8.x4.shared.b16 {%0,%1,%2,%3}, [%4];"
                 : "=r"(r[0]), "=r"(r[1]), "=r"(r[2]), "=r"(r[3]) : "r"(addr));
}
__device__ __forceinline__ void ldsm4t(uint32_t* r, uint32_t addr) {
    asm volatile("ldmatrix.sync.aligned.m8n8.x4.trans.shared.b16 {%0,%1,%2,%3}, [%4];"
                 : "=r"(r[0]), "=r"(r[1]), "=r"(r[2]), "=r"(r[3]) : "r"(addr));
}
// group g=lane>>3: row = r0 + (lane&7) + 8*(g&1); colByte += 16*(g>>1)
__device__ __forceinline__ uint32_t lane_addr(uint32_t base, int lane, int pitch) {
    int g = lane >> 3;
    int row = (lane & 7) + ((g & 1) << 3);
    return base + row * pitch + ((g >> 1) << 4);
}
__device__ __forceinline__ void mma_bf16(float* d, const uint32_t* a, uint32_t b0, uint32_t b1) {
    asm volatile(
        "mma.sync.aligned.m16n8k16.row.col.f32.bf16.bf16.f32 "
        "{%0,%1,%2,%3}, {%4,%5,%6,%7}, {%8,%9}, {%0,%1,%2,%3};"
        : "+f"(d[0]), "+f"(d[1]), "+f"(d[2]), "+f"(d[3])
        : "r"(a[0]), "r"(a[1]), "r"(a[2]), "r"(a[3]), "r"(b0), "r"(b1));
}
__device__ __forceinline__ uint32_t pack2(float lo, float hi) {
    uint32_t r;
    asm("cvt.rn.bf16x2.f32 %0, %1, %2;" : "=r"(r) : "f"(hi), "f"(lo));
    return r;
}
__device__ __forceinline__ void split2(float v0, float v1, uint32_t& hi, uint32_t& lo) {
    float h0 = __bfloat162float(__float2bfloat16_rn(v0));
    float h1 = __bfloat162float(__float2bfloat16_rn(v1));
    hi = pack2(h0, h1);
    lo = pack2(v0 - h0, v1 - h1);
}

// ---------------- table init ----------------
__global__ void init_tables() {
    int tid = blockIdx.x * blockDim.x + threadIdx.x;
    if (tid < SEQ * NPAIR) {
        int n = tid / NPAIR, p = tid % NPAIR;
        float x = (float)p / 31.0f;
        float theta = (float)exp(-(double)x * 9.210340371976184);
        float ang = (float)n * theta;
        g_sin[tid] = (float)sin((double)ang);
        g_cos[tid] = (float)cos((double)ang);
    }
    if (tid < HEADS * SEQ) {
        int h = tid / SEQ, dist = tid % SEQ;
        double t = (double)h / 15.0;
        float l = (float)((1.0 - t) * (-3.4657359027997265) + t * (-6.238324625039508));
        float gamma = 1.0f - expf(l);
        g_gpow[tid] = (float)exp((double)dist * log((double)gamma));
    }
}

// ---------------- fp32 -> bf16 hi/lo split ----------------
__global__ void convert_pair(const float* __restrict__ src,
                             bf16* __restrict__ hi, bf16* __restrict__ lo, int n) {
    int i = blockIdx.x * blockDim.x + threadIdx.x;
    if (i < n) {
        float x = src[i];
        bf16 h = __float2bfloat16_rn(x);
        hi[i] = h;
        lo[i] = __float2bfloat16_rn(x - __bfloat162float(h));
    }
}

// ---------------- mma.sync GEMM: C[m][j] = sum_k A[m][k]*W[j][k] + b[j] ----------------
// 3-term bf16 split: Ah*Wh + Ah*Wl + Al*Wh. Tile 128x128, K-chunk 32, 8 warps (warp 32x64).
// MODE 0: plain f32 (B,N,E)    1: RoPE -> bf16 hi/lo (B,H,N,D)
// MODE 2: RoPE/8 -> bf16 hi/lo (B,H,N,D)   3: plain -> bf16 hi/lo (B,H,N,D)
// MODE 4: SiLU f32 (B,N,E)
#define GPITCH 80                // bytes/row: 32 bf16 (64B) + 16B pad -> conflict-free ldmatrix
#define GTILE  (128*GPITCH)      // 10240
#define GSTAGE (4*GTILE)         // 40960
#define GSMEM  (2*GSTAGE)        // 81920

template<int MODE>
__global__ __launch_bounds__(256, 2) void gemm_mma(
        const bf16* __restrict__ Ah, const bf16* __restrict__ Al,
        const bf16* __restrict__ Wh, const bf16* __restrict__ Wl,
        const float* __restrict__ bias,
        float* __restrict__ Cf, bf16* __restrict__ Chi, bf16* __restrict__ Clo) {
    extern __shared__ char sm[];
    const uint32_t sb = smem_u32(sm);
    const int tid = threadIdx.x;
    const int lane = tid & 31, wid = tid >> 5;
    const int warpM = wid & 3, warpN = wid >> 2;
    const int m0 = blockIdx.y * 128, j0 = blockIdx.x * 128;

    const bf16* srcs[4] = { Ah + (size_t)m0 * EMB, Al + (size_t)m0 * EMB,
                            Wh + (size_t)j0 * EMB, Wl + (size_t)j0 * EMB };

    auto issue = [&](int c) {
        const int k0 = c * 32;
        const uint32_t stg = sb + (c & 1) * GSTAGE;
#pragma unroll
        for (int i = 0; i < 8; ++i) {
            int s = tid + 256 * i;
            int t = s >> 9;
            int local = s & 511;
            int row = local >> 2, s4 = local & 3;
            cp16(stg + t * GTILE + row * GPITCH + s4 * 16,
                 srcs[t] + (size_t)row * EMB + k0 + s4 * 8);
        }
        CP_COMMIT();
    };

    float acc[2][8][4];
#pragma unroll
    for (int a = 0; a < 2; ++a)
#pragma unroll
        for (int b = 0; b < 8; ++b)
#pragma unroll
            for (int c = 0; c < 4; ++c) acc[a][b][c] = 0.f;

    issue(0);
    for (int c = 0; c < 32; ++c) {
        if (c < 31) { issue(c + 1); CP_WAIT1(); } else { CP_WAIT0(); }
        __syncthreads();
        const uint32_t st = sb + (c & 1) * GSTAGE;
#pragma unroll
        for (int ks = 0; ks < 2; ++ks) {
            const int kb = ks * 32;
            uint32_t ah[2][4], al[2][4], bb[4][4];
#pragma unroll
            for (int mf = 0; mf < 2; ++mf) {
                uint32_t rbase = st + (32 * warpM + 16 * mf) * GPITCH + kb;
                ldsm4(ah[mf], lane_addr(rbase, lane, GPITCH));
                ldsm4(al[mf], lane_addr(rbase + GTILE, lane, GPITCH));
            }
#pragma unroll
            for (int nf = 0; nf < 4; ++nf)
                ldsm4(bb[nf], lane_addr(st + 2 * GTILE + (64 * warpN + 16 * nf) * GPITCH + kb, lane, GPITCH));
#pragma unroll
            for (int mf = 0; mf < 2; ++mf)
#pragma unroll
                for (int nf = 0; nf < 4; ++nf) {
                    mma_bf16(acc[mf][2 * nf],     ah[mf], bb[nf][0], bb[nf][2]);
                    mma_bf16(acc[mf][2 * nf + 1], ah[mf], bb[nf][1], bb[nf][3]);
                    mma_bf16(acc[mf][2 * nf],     al[mf], bb[nf][0], bb[nf][2]);
                    mma_bf16(acc[mf][2 * nf + 1], al[mf], bb[nf][1], bb[nf][3]);
                }
#pragma unroll
            for (int nf = 0; nf < 4; ++nf)
                ldsm4(bb[nf], lane_addr(st + 3 * GTILE + (64 * warpN + 16 * nf) * GPITCH + kb, lane, GPITCH));
#pragma unroll
            for (int mf = 0; mf < 2; ++mf)
#pragma unroll
                for (int nf = 0; nf < 4; ++nf) {
                    mma_bf16(acc[mf][2 * nf],     ah[mf], bb[nf][0], bb[nf][2]);
                    mma_bf16(acc[mf][2 * nf + 1], ah[mf], bb[nf][1], bb[nf][3]);
                }
        }
        __syncthreads();
    }

    // epilogue
    const int quad = lane >> 2, qlane = lane & 3;
#pragma unroll
    for (int mf = 0; mf < 2; ++mf) {
#pragma unroll
        for (int half = 0; half < 2; ++half) {
            int r = 32 * warpM + 16 * mf + quad + half * 8;
            int m = m0 + r;
            int bb_ = m >> 11, n = m & (SEQ - 1);
#pragma unroll
            for (int nf = 0; nf < 8; ++nf) {
                int col = j0 + 64 * warpN + 8 * nf + 2 * qlane;
                float v0 = acc[mf][nf][half * 2 + 0] + __ldg(bias + col);
                float v1 = acc[mf][nf][half * 2 + 1] + __ldg(bias + col + 1);
                if (MODE == 1 || MODE == 2) {
                    int p = (col & 63) >> 1;
                    float s = g_sin[n * NPAIR + p], cs = g_cos[n * NPAIR + p];
                    float t0 = v0 * cs - v1 * s;
                    float t1 = v1 * cs + v0 * s;
                    v0 = t0; v1 = t1;
                    if (MODE == 2) { v0 *= 0.125f; v1 *= 0.125f; }
                }
                if (MODE == 4) {
                    v0 = v0 / (1.f + expf(-v0));
                    v1 = v1 / (1.f + expf(-v1));
                }
                if (MODE == 0 || MODE == 4) {
                    *(float2*)(Cf + (size_t)(bb_ * SEQ + n) * EMB + col) = make_float2(v0, v1);
                } else {
                    int hh_ = col >> 6, d = col & 63;
                    size_t idx = ((size_t)((bb_ * HEADS + hh_) * SEQ + n)) * HDIM + d;
                    uint32_t uh, ul;
                    split2(v0, v1, uh, ul);
                    *(uint32_t*)(Chi + idx) = uh;
                    *(uint32_t*)(Clo + idx) = ul;
                }
            }
        }
    }
}

// ---------------- retention attention via mma.sync ----------------
// 128 threads (4 warps), q-tile 64, kv-tile 64. Warp w owns S/O rows 16w..16w+15.
// S = q.k^T (3-term split), decay+causal on f32 acc, P repacked in-register (FA2 trick),
// O += P.v via ldmatrix.trans (3-term split). Groupnorm + gate fused.
#define APITCH 144               // bytes/row: 64 bf16 (128B) + 16B pad
#define ATILE  (64*APITCH)       // 9216
#define AT_SMEM (6*ATILE + SEQ*4)   // 63488

__global__ __launch_bounds__(128) void attention_mma() {
    extern __shared__ char sm[];
    const uint32_t sb = smem_u32(sm);
    float* spg = (float*)(sm + 6 * ATILE);

    const int tid = threadIdx.x;
    const int lane = tid & 31, wid = tid >> 5;
    const int quad = lane >> 2, qlane = lane & 3;
    const int qt = 31 - blockIdx.x;     // heavy blocks launch first
    const int h = blockIdx.y, b = blockIdx.z;
    const int q0 = qt * 64;
    const size_t headbase = (size_t)(b * HEADS + h) * SEQ * HDIM;

    // stage q tiles + gp
    {
        const bf16* qhp = g_qh + headbase + (size_t)q0 * HDIM;
        const bf16* qlp = g_ql + headbase + (size_t)q0 * HDIM;
#pragma unroll
        for (int i = 0; i < 8; ++i) {
            int s = tid + 128 * i;
            int t = s >> 9;
            int local = s & 511;
            int row = local >> 3, s8 = local & 7;
            cp16(sb + t * ATILE + row * APITCH + s8 * 16,
                 (t ? qlp : qhp) + (size_t)row * HDIM + s8 * 8);
        }
#pragma unroll
        for (int i = 0; i < 4; ++i) {
            int s = tid + 128 * i;
            cp16(sb + 6 * ATILE + s * 16, g_gpow + h * SEQ + s * 4);
        }
        CP_COMMIT();
    }

    float oacc[8][4];
#pragma unroll
    for (int f = 0; f < 8; ++f)
#pragma unroll
        for (int c = 0; c < 4; ++c) oacc[f][c] = 0.f;

    const bf16* khp = g_kh + headbase;
    const bf16* klp = g_kl + headbase;
    const bf16* vhp = g_vh + headbase;
    const bf16* vlp = g_vl + headbase;

    for (int kt = 0; kt <= qt; ++kt) {
        const int k0 = kt * 64;
        __syncthreads();   // prev iter consumers done before overwrite
        {
            const bf16* srcs[4] = { khp + (size_t)k0 * HDIM, klp + (size_t)k0 * HDIM,
                                    vhp + (size_t)k0 * HDIM, vlp + (size_t)k0 * HDIM };
#pragma unroll
            for (int i = 0; i < 16; ++i) {
                int s = tid + 128 * i;
                int t = s >> 9;
                int local = s & 511;
                int row = local >> 3, s8 = local & 7;
                cp16(sb + (2 + t) * ATILE + row * APITCH + s8 * 16,
                     srcs[t] + (size_t)row * HDIM + s8 * 8);
            }
            CP_COMMIT();
        }
        CP_WAIT0();
        __syncthreads();

        // ---- S = q.k^T ----
        float sacc[8][4];
#pragma unroll
        for (int f = 0; f < 8; ++f)
#pragma unroll
            for (int c = 0; c < 4; ++c) sacc[f][c] = 0.f;

#pragma unroll
        for (int ks = 0; ks < 4; ++ks) {
            const int kb = ks * 32;
            uint32_t qh4[4], ql4[4];
            ldsm4(qh4, lane_addr(sb + 0 * ATILE + (16 * wid) * APITCH + kb, lane, APITCH));
            ldsm4(ql4, lane_addr(sb + 1 * ATILE + (16 * wid) * APITCH + kb, lane, APITCH));
#pragma unroll
            for (int jf = 0; jf < 4; ++jf) {
                uint32_t kh4[4], kl4[4];
                ldsm4(kh4, lane_addr(sb + 2 * ATILE + (16 * jf) * APITCH + kb, lane, APITCH));
                ldsm4(kl4, lane_addr(sb + 3 * ATILE + (16 * jf) * APITCH + kb, lane, APITCH));
                mma_bf16(sacc[2 * jf],     qh4, kh4[0], kh4[2]);
                mma_bf16(sacc[2 * jf + 1], qh4, kh4[1], kh4[3]);
                mma_bf16(sacc[2 * jf],     qh4, kl4[0], kl4[2]);
                mma_bf16(sacc[2 * jf + 1], qh4, kl4[1], kl4[3]);
                mma_bf16(sacc[2 * jf],     ql4, kh4[0], kh4[2]);
                mma_bf16(sacc[2 * jf + 1], ql4, kh4[1], kh4[3]);
            }
        }

        // ---- decay + causal ----
        const int dist0 = (qt - kt) * 64;
#pragma unroll
        for (int f = 0; f < 8; ++f) {
#pragma unroll
            for (int c = 0; c < 4; ++c) {
                int j = 8 * f + 2 * qlane + (c & 1);
                int i = 16 * wid + quad + ((c >> 1) << 3);
                int idx = dist0 + i - j;
                float w = (idx >= 0) ? spg[idx] : 0.f;
                sacc[f][c] *= w;
            }
        }

        // ---- pack P (A-fragments for O-mma) ----
        uint32_t phi[4][4], plo[4][4];
#pragma unroll
        for (int s = 0; s < 4; ++s) {
            split2(sacc[2 * s][0],     sacc[2 * s][1],     phi[s][0], plo[s][0]);
            split2(sacc[2 * s][2],     sacc[2 * s][3],     phi[s][1], plo[s][1]);
            split2(sacc[2 * s + 1][0], sacc[2 * s + 1][1], phi[s][2], plo[s][2]);
            split2(sacc[2 * s + 1][2], sacc[2 * s + 1][3], phi[s][3], plo[s][3]);
        }

        // ---- O += P.v ----
#pragma unroll
        for (int s = 0; s < 4; ++s) {
#pragma unroll
            for (int g = 0; g < 4; ++g) {
                uint32_t vh4[4], vl4[4];
                ldsm4t(vh4, lane_addr(sb + 4 * ATILE + (16 * s) * APITCH + g * 32, lane, APITCH));
                ldsm4t(vl4, lane_addr(sb + 5 * ATILE + (16 * s) * APITCH + g * 32, lane, APITCH));
                mma_bf16(oacc[2 * g],     phi[s], vh4[0], vh4[1]);
                mma_bf16(oacc[2 * g + 1], phi[s], vh4[2], vh4[3]);
                mma_bf16(oacc[2 * g],     phi[s], vl4[0], vl4[1]);
                mma_bf16(oacc[2 * g + 1], phi[s], vl4[2], vl4[3]);
                mma_bf16(oacc[2 * g],     plo[s], vh4[0], vh4[1]);
                mma_bf16(oacc[2 * g + 1], plo[s], vh4[2], vh4[3]);
            }
        }
    }

    // ---- groupnorm (per row over 64 dims) via quad shuffles ----
    float sA = 0.f, sB = 0.f;
#pragma unroll
    for (int f = 0; f < 8; ++f) { sA += oacc[f][0] + oacc[f][1]; sB += oacc[f][2] + oacc[f][3]; }
    sA += __shfl_xor_sync(0xFFFFFFFFu, sA, 1); sA += __shfl_xor_sync(0xFFFFFFFFu, sA, 2);
    sB += __shfl_xor_sync(0xFFFFFFFFu, sB, 1); sB += __shfl_xor_sync(0xFFFFFFFFu, sB, 2);
    float mA = sA * (1.f / 64.f), mB = sB * (1.f / 64.f);
    float vA = 0.f, vB = 0.f;
#pragma unroll
    for (int f = 0; f < 8; ++f) {
        float d0 = oacc[f][0] - mA, d1 = oacc[f][1] - mA;
        float d2 = oacc[f][2] - mB, d3 = oacc[f][3] - mB;
        vA += d0 * d0 + d1 * d1;
        vB += d2 * d2 + d3 * d3;
    }
    vA += __shfl_xor_sync(0xFFFFFFFFu, vA, 1); vA += __shfl_xor_sync(0xFFFFFFFFu, vA, 2);
    vB += __shfl_xor_sync(0xFFFFFFFFu, vB, 1); vB += __shfl_xor_sync(0xFFFFFFFFu, vB, 2);
    float rA = rsqrtf(vA * (1.f / 64.f) + 1e-6f);
    float rB = rsqrtf(vB * (1.f / 64.f) + 1e-6f);

    // ---- gate + write hidden (bf16 hi/lo, layout B,N,E) ----
    const int iA = q0 + 16 * wid + quad;
    const int iB = iA + 8;
#pragma unroll
    for (int f = 0; f < 8; ++f) {
        int d = 8 * f + 2 * qlane;
        size_t eA = (size_t)(b * SEQ + iA) * EMB + h * HDIM + d;
        size_t eB = (size_t)(b * SEQ + iB) * EMB + h * HDIM + d;
        float2 gA = *(const float2*)(g_gate + eA);
        float2 gB = *(const float2*)(g_gate + eB);
        float x0 = (oacc[f][0] - mA) * rA * gA.x;
        float x1 = (oacc[f][1] - mA) * rA * gA.y;
        float y0 = (oacc[f][2] - mB) * rB * gB.x;
        float y1 = (oacc[f][3] - mB) * rB * gB.y;
        uint32_t uh, ul;
        split2(x0, x1, uh, ul);
        *(uint32_t*)(g_hh + eA) = uh;
        *(uint32_t*)(g_hl + eA) = ul;
        split2(y0, y1, uh, ul);
        *(uint32_t*)(g_hh + eB) = uh;
        *(uint32_t*)(g_hl + eB) = ul;
    }
}

// ---------------- launch ----------------
extern "C" void kernel_launch(void* const* d_in, const int* in_sizes, int n_in,
                              void* d_out, int out_size) {
    const float* query  = (const float*)d_in[0];
    const float* key_in = (const float*)d_in[1];
    const float* value  = (const float*)d_in[2];
    const float* Wq = (const float*)d_in[3];
    const float* bq = (const float*)d_in[4];
    const float* Wk = (const float*)d_in[5];
    const float* bk = (const float*)d_in[6];
    const float* Wv = (const float*)d_in[7];
    const float* bv = (const float*)d_in[8];
    const float* Wg = (const float*)d_in[9];
    const float* bg = (const float*)d_in[10];
    const float* Wo = (const float*)d_in[11];
    const float* bo = (const float*)d_in[12];
    float* out = (float*)d_out;

    float* gatep;
    cudaGetSymbolAddress((void**)&gatep, g_gate);

    bf16 *xqh,*xql,*xkh,*xkl,*xvh,*xvl,*hh,*hl;
    bf16 *wqh,*wql,*wkh,*wkl,*wvh,*wvl,*wgh,*wgl,*woh,*wol;
    bf16 *qh,*ql,*kh,*kl,*vh,*vl;
    cudaGetSymbolAddress((void**)&xqh, g_xqh); cudaGetSymbolAddress((void**)&xql, g_xql);
    cudaGetSymbolAddress((void**)&xkh, g_xkh); cudaGetSymbolAddress((void**)&xkl, g_xkl);
    cudaGetSymbolAddress((void**)&xvh, g_xvh); cudaGetSymbolAddress((void**)&xvl, g_xvl);
    cudaGetSymbolAddress((void**)&hh, g_hh);   cudaGetSymbolAddress((void**)&hl, g_hl);
    cudaGetSymbolAddress((void**)&wqh, g_wqh); cudaGetSymbolAddress((void**)&wql, g_wql);
    cudaGetSymbolAddress((void**)&wkh, g_wkh); cudaGetSymbolAddress((void**)&wkl, g_wkl);
    cudaGetSymbolAddress((void**)&wvh, g_wvh); cudaGetSymbolAddress((void**)&wvl, g_wvl);
    cudaGetSymbolAddress((void**)&wgh, g_wgh); cudaGetSymbolAddress((void**)&wgl, g_wgl);
    cudaGetSymbolAddress((void**)&woh, g_woh); cudaGetSymbolAddress((void**)&wol, g_wol);
    cudaGetSymbolAddress((void**)&qh, g_qh);   cudaGetSymbolAddress((void**)&ql, g_ql);
    cudaGetSymbolAddress((void**)&kh, g_kh);   cudaGetSymbolAddress((void**)&kl, g_kl);
    cudaGetSymbolAddress((void**)&vh, g_vh);   cudaGetSymbolAddress((void**)&vl, g_vl);

    cudaFuncSetAttribute(gemm_mma<0>, cudaFuncAttributeMaxDynamicSharedMemorySize, GSMEM);
    cudaFuncSetAttribute(gemm_mma<1>, cudaFuncAttributeMaxDynamicSharedMemorySize, GSMEM);
    cudaFuncSetAttribute(gemm_mma<2>, cudaFuncAttributeMaxDynamicSharedMemorySize, GSMEM);
    cudaFuncSetAttribute(gemm_mma<3>, cudaFuncAttributeMaxDynamicSharedMemorySize, GSMEM);
    cudaFuncSetAttribute(gemm_mma<4>, cudaFuncAttributeMaxDynamicSharedMemorySize, GSMEM);
    cudaFuncSetAttribute(attention_mma, cudaFuncAttributeMaxDynamicSharedMemorySize, AT_SMEM);

    init_tables<<<256, 256>>>();

    const int NA = MROWS * EMB;
    const int NW = EMB * EMB;
    convert_pair<<<(NA + 255) / 256, 256>>>(query,  xqh, xql, NA);
    convert_pair<<<(NA + 255) / 256, 256>>>(key_in, xkh, xkl, NA);
    convert_pair<<<(NA + 255) / 256, 256>>>(value,  xvh, xvl, NA);
    convert_pair<<<(NW + 255) / 256, 256>>>(Wq, wqh, wql, NW);
    convert_pair<<<(NW + 255) / 256, 256>>>(Wk, wkh, wkl, NW);
    convert_pair<<<(NW + 255) / 256, 256>>>(Wv, wvh, wvl, NW);
    convert_pair<<<(NW + 255) / 256, 256>>>(Wg, wgh, wgl, NW);
    convert_pair<<<(NW + 255) / 256, 256>>>(Wo, woh, wol, NW);

    dim3 gg(EMB / 128, MROWS / 128);   // (8, 32)
    gemm_mma<1><<<gg, 256, GSMEM>>>(xqh, xql, wqh, wql, bq, nullptr, qh, ql);
    gemm_mma<2><<<gg, 256, GSMEM>>>(xkh, xkl, wkh, wkl, bk, nullptr, kh, kl);
    gemm_mma<3><<<gg, 256, GSMEM>>>(xvh, xvl, wvh, wvl, bv, nullptr, vh, vl);
    gemm_mma<4><<<gg, 256, GSMEM>>>(xqh, xql, wgh, wgl, bg, gatep, nullptr, nullptr);

    attention_mma<<<dim3(SEQ / 64, HEADS, BATCH), 128, AT_SMEM>>>();

    gemm_mma<0><<<gg, 256, GSMEM>>>(hh, hl, woh, wol, bo, out, nullptr, nullptr);
}

// round 5
// speedup vs baseline: 2.1100x; 1.0074x over previous
#include <cuda_runtime.h>
#include <cuda_bf16.h>
#include <math.h>
#include <stdint.h>

#define BATCH 2
#define SEQ   2048
#define EMB   1024
#define HEADS 16
#define HDIM  64
#define NPAIR 32
#define MROWS (BATCH*SEQ)   // 4096

typedef __nv_bfloat16 bf16;

// ---------------- scratch (device globals; no allocation allowed) ----------------
__device__ float g_gate[BATCH*SEQ*EMB];
__device__ float g_sin[SEQ*NPAIR];
__device__ float g_cos[SEQ*NPAIR];
__device__ float g_gpow[HEADS*SEQ];

__device__ __align__(16) bf16 g_xqh[MROWS*EMB], g_xql[MROWS*EMB];
__device__ __align__(16) bf16 g_xkh[MROWS*EMB], g_xkl[MROWS*EMB];
__device__ __align__(16) bf16 g_xvh[MROWS*EMB], g_xvl[MROWS*EMB];
__device__ __align__(16) bf16 g_hh [MROWS*EMB], g_hl [MROWS*EMB];
__device__ __align__(16) bf16 g_wqh[EMB*EMB], g_wql[EMB*EMB];
__device__ __align__(16) bf16 g_wkh[EMB*EMB], g_wkl[EMB*EMB];
__device__ __align__(16) bf16 g_wvh[EMB*EMB], g_wvl[EMB*EMB];
__device__ __align__(16) bf16 g_wgh[EMB*EMB], g_wgl[EMB*EMB];
__device__ __align__(16) bf16 g_woh[EMB*EMB], g_wol[EMB*EMB];
__device__ __align__(16) bf16 g_qh[MROWS*EMB], g_ql[MROWS*EMB];
__device__ __align__(16) bf16 g_kh[MROWS*EMB], g_kl[MROWS*EMB];
__device__ __align__(16) bf16 g_vh[MROWS*EMB], g_vl[MROWS*EMB];

// ---------------- helpers ----------------
__device__ __forceinline__ uint32_t smem_u32(const void* p) {
    uint32_t a;
    asm("{ .reg .u64 t; cvta.to.shared.u64 t, %1; cvt.u32.u64 %0, t; }" : "=r"(a) : "l"(p));
    return a;
}
__device__ __forceinline__ void cp16(uint32_t dst, const void* src) {
    asm volatile("cp.async.cg.shared.global [%0], [%1], 16;" :: "r"(dst), "l"(src));
}
#define CP_COMMIT() asm volatile("cp.async.commit_group;" ::: "memory")
#define CP_WAIT0()  asm volatile("cp.async.wait_group 0;" ::: "memory")
#define CP_WAIT1()  asm volatile("cp.async.wait_group 1;" ::: "memory")

__device__ __forceinline__ void ldsm4(uint32_t* r, uint32_t addr) {
    asm volatile("ldmatrix.sync.aligned.m8n8.x4.shared.b16 {%0,%1,%2,%3}, [%4];"
                 : "=r"(r[0]), "=r"(r[1]), "=r"(r[2]), "=r"(r[3]) : "r"(addr));
}
__device__ __forceinline__ void ldsm4t(uint32_t* r, uint32_t addr) {
    asm volatile("ldmatrix.sync.aligned.m8n8.x4.trans.shared.b16 {%0,%1,%2,%3}, [%4];"
                 : "=r"(r[0]), "=r"(r[1]), "=r"(r[2]), "=r"(r[3]) : "r"(addr));
}
// group g=lane>>3: row = r0 + (lane&7) + 8*(g&1); colByte += 16*(g>>1)
__device__ __forceinline__ uint32_t lane_addr(uint32_t base, int lane, int pitch) {
    int g = lane >> 3;
    int row = (lane & 7) + ((g & 1) << 3);
    return base + row * pitch + ((g >> 1) << 4);
}
__device__ __forceinline__ void mma_bf16(float* d, const uint32_t* a, uint32_t b0, uint32_t b1) {
    asm volatile(
        "mma.sync.aligned.m16n8k16.row.col.f32.bf16.bf16.f32 "
        "{%0,%1,%2,%3}, {%4,%5,%6,%7}, {%8,%9}, {%0,%1,%2,%3};"
        : "+f"(d[0]), "+f"(d[1]), "+f"(d[2]), "+f"(d[3])
        : "r"(a[0]), "r"(a[1]), "r"(a[2]), "r"(a[3]), "r"(b0), "r"(b1));
}
__device__ __forceinline__ uint32_t pack2(float lo, float hi) {
    uint32_t r;
    asm("cvt.rn.bf16x2.f32 %0, %1, %2;" : "=r"(r) : "f"(hi), "f"(lo));
    return r;
}
__device__ __forceinline__ void split2(float v0, float v1, uint32_t& hi, uint32_t& lo) {
    float h0 = __bfloat162float(__float2bfloat16_rn(v0));
    float h1 = __bfloat162float(__float2bfloat16_rn(v1));
    hi = pack2(h0, h1);
    lo = pack2(v0 - h0, v1 - h1);
}

// ---------------- table init ----------------
__global__ void init_tables() {
    int tid = blockIdx.x * blockDim.x + threadIdx.x;
    if (tid < SEQ * NPAIR) {
        int n = tid / NPAIR, p = tid % NPAIR;
        float x = (float)p / 31.0f;
        float theta = (float)exp(-(double)x * 9.210340371976184);
        float ang = (float)n * theta;
        g_sin[tid] = (float)sin((double)ang);
        g_cos[tid] = (float)cos((double)ang);
    }
    if (tid < HEADS * SEQ) {
        int h = tid / SEQ, dist = tid % SEQ;
        double t = (double)h / 15.0;
        float l = (float)((1.0 - t) * (-3.4657359027997265) + t * (-6.238324625039508));
        float gamma = 1.0f - expf(l);
        g_gpow[tid] = (float)exp((double)dist * log((double)gamma));
    }
}

// ---------------- fp32 -> bf16 hi/lo split (vectorized x4) ----------------
__global__ void convert_pair4(const float4* __restrict__ src,
                              uint2* __restrict__ hi, uint2* __restrict__ lo, int n4) {
    int i = blockIdx.x * blockDim.x + threadIdx.x;
    if (i < n4) {
        float4 x = src[i];
        uint32_t h0, l0, h1, l1;
        split2(x.x, x.y, h0, l0);
        split2(x.z, x.w, h1, l1);
        hi[i] = make_uint2(h0, h1);
        lo[i] = make_uint2(l0, l1);
    }
}

// ---------------- mma.sync GEMM (unchanged from R4) ----------------
#define GPITCH 80
#define GTILE  (128*GPITCH)
#define GSTAGE (4*GTILE)
#define GSMEM  (2*GSTAGE)

template<int MODE>
__global__ __launch_bounds__(256, 2) void gemm_mma(
        const bf16* __restrict__ Ah, const bf16* __restrict__ Al,
        const bf16* __restrict__ Wh, const bf16* __restrict__ Wl,
        const float* __restrict__ bias,
        float* __restrict__ Cf, bf16* __restrict__ Chi, bf16* __restrict__ Clo) {
    extern __shared__ char sm[];
    const uint32_t sb = smem_u32(sm);
    const int tid = threadIdx.x;
    const int lane = tid & 31, wid = tid >> 5;
    const int warpM = wid & 3, warpN = wid >> 2;
    const int m0 = blockIdx.y * 128, j0 = blockIdx.x * 128;

    const bf16* srcs[4] = { Ah + (size_t)m0 * EMB, Al + (size_t)m0 * EMB,
                            Wh + (size_t)j0 * EMB, Wl + (size_t)j0 * EMB };

    auto issue = [&](int c) {
        const int k0 = c * 32;
        const uint32_t stg = sb + (c & 1) * GSTAGE;
#pragma unroll
        for (int i = 0; i < 8; ++i) {
            int s = tid + 256 * i;
            int t = s >> 9;
            int local = s & 511;
            int row = local >> 2, s4 = local & 3;
            cp16(stg + t * GTILE + row * GPITCH + s4 * 16,
                 srcs[t] + (size_t)row * EMB + k0 + s4 * 8);
        }
        CP_COMMIT();
    };

    float acc[2][8][4];
#pragma unroll
    for (int a = 0; a < 2; ++a)
#pragma unroll
        for (int b = 0; b < 8; ++b)
#pragma unroll
            for (int c = 0; c < 4; ++c) acc[a][b][c] = 0.f;

    issue(0);
    for (int c = 0; c < 32; ++c) {
        if (c < 31) { issue(c + 1); CP_WAIT1(); } else { CP_WAIT0(); }
        __syncthreads();
        const uint32_t st = sb + (c & 1) * GSTAGE;
#pragma unroll
        for (int ks = 0; ks < 2; ++ks) {
            const int kb = ks * 32;
            uint32_t ah[2][4], al[2][4], bb[4][4];
#pragma unroll
            for (int mf = 0; mf < 2; ++mf) {
                uint32_t rbase = st + (32 * warpM + 16 * mf) * GPITCH + kb;
                ldsm4(ah[mf], lane_addr(rbase, lane, GPITCH));
                ldsm4(al[mf], lane_addr(rbase + GTILE, lane, GPITCH));
            }
#pragma unroll
            for (int nf = 0; nf < 4; ++nf)
                ldsm4(bb[nf], lane_addr(st + 2 * GTILE + (64 * warpN + 16 * nf) * GPITCH + kb, lane, GPITCH));
#pragma unroll
            for (int mf = 0; mf < 2; ++mf)
#pragma unroll
                for (int nf = 0; nf < 4; ++nf) {
                    mma_bf16(acc[mf][2 * nf],     ah[mf], bb[nf][0], bb[nf][2]);
                    mma_bf16(acc[mf][2 * nf + 1], ah[mf], bb[nf][1], bb[nf][3]);
                    mma_bf16(acc[mf][2 * nf],     al[mf], bb[nf][0], bb[nf][2]);
                    mma_bf16(acc[mf][2 * nf + 1], al[mf], bb[nf][1], bb[nf][3]);
                }
#pragma unroll
            for (int nf = 0; nf < 4; ++nf)
                ldsm4(bb[nf], lane_addr(st + 3 * GTILE + (64 * warpN + 16 * nf) * GPITCH + kb, lane, GPITCH));
#pragma unroll
            for (int mf = 0; mf < 2; ++mf)
#pragma unroll
                for (int nf = 0; nf < 4; ++nf) {
                    mma_bf16(acc[mf][2 * nf],     ah[mf], bb[nf][0], bb[nf][2]);
                    mma_bf16(acc[mf][2 * nf + 1], ah[mf], bb[nf][1], bb[nf][3]);
                }
        }
        __syncthreads();
    }

    const int quad = lane >> 2, qlane = lane & 3;
#pragma unroll
    for (int mf = 0; mf < 2; ++mf) {
#pragma unroll
        for (int half = 0; half < 2; ++half) {
            int r = 32 * warpM + 16 * mf + quad + half * 8;
            int m = m0 + r;
            int bb_ = m >> 11, n = m & (SEQ - 1);
#pragma unroll
            for (int nf = 0; nf < 8; ++nf) {
                int col = j0 + 64 * warpN + 8 * nf + 2 * qlane;
                float v0 = acc[mf][nf][half * 2 + 0] + __ldg(bias + col);
                float v1 = acc[mf][nf][half * 2 + 1] + __ldg(bias + col + 1);
                if (MODE == 1 || MODE == 2) {
                    int p = (col & 63) >> 1;
                    float s = g_sin[n * NPAIR + p], cs = g_cos[n * NPAIR + p];
                    float t0 = v0 * cs - v1 * s;
                    float t1 = v1 * cs + v0 * s;
                    v0 = t0; v1 = t1;
                    if (MODE == 2) { v0 *= 0.125f; v1 *= 0.125f; }
                }
                if (MODE == 4) {
                    v0 = v0 / (1.f + expf(-v0));
                    v1 = v1 / (1.f + expf(-v1));
                }
                if (MODE == 0 || MODE == 4) {
                    *(float2*)(Cf + (size_t)(bb_ * SEQ + n) * EMB + col) = make_float2(v0, v1);
                } else {
                    int hh_ = col >> 6, d = col & 63;
                    size_t idx = ((size_t)((bb_ * HEADS + hh_) * SEQ + n)) * HDIM + d;
                    uint32_t uh, ul;
                    split2(v0, v1, uh, ul);
                    *(uint32_t*)(Chi + idx) = uh;
                    *(uint32_t*)(Clo + idx) = ul;
                }
            }
        }
    }
}

// ---------------- retention attention: 256 threads, q-tile 128, 2-stage kv ----------------
#define APITCH 144               // 64 bf16 (128B) + 16B pad
#define AKTILE (64*APITCH)       // 9216
#define AQTILE (128*APITCH)      // 18432
#define AKV_BASE (2*AQTILE)      // 36864
#define AGP_BASE (AKV_BASE + 2*4*AKTILE)   // 110592
#define AT_SMEM  (AGP_BASE + SEQ*4)        // 118784

__global__ __launch_bounds__(256) void attention_mma() {
    extern __shared__ char sm[];
    const uint32_t sb = smem_u32(sm);
    float* spg = (float*)(sm + AGP_BASE);

    const int tid = threadIdx.x;
    const int lane = tid & 31, wid = tid >> 5;          // wid 0..7
    const int quad = lane >> 2, qlane = lane & 3;
    const int qt = (SEQ / 128 - 1) - blockIdx.x;        // heavy blocks first
    const int h = blockIdx.y, b = blockIdx.z;
    const int q0 = qt * 128;
    const size_t headbase = (size_t)(b * HEADS + h) * SEQ * HDIM;

    // stage q (hi/lo) + gp
    {
        const bf16* qhp = g_qh + headbase + (size_t)q0 * HDIM;
        const bf16* qlp = g_ql + headbase + (size_t)q0 * HDIM;
#pragma unroll
        for (int i = 0; i < 8; ++i) {
            int s = tid + 256 * i;
            int t = s >> 10;
            int local = s & 1023;
            int row = local >> 3, s8 = local & 7;
            cp16(sb + t * AQTILE + row * APITCH + s8 * 16,
                 (t ? qlp : qhp) + (size_t)row * HDIM + s8 * 8);
        }
#pragma unroll
        for (int i = 0; i < 2; ++i) {
            int s = tid + 256 * i;
            cp16(sb + AGP_BASE + s * 16, g_gpow + h * SEQ + s * 4);
        }
        CP_COMMIT();
    }

    float oacc[8][4];
#pragma unroll
    for (int f = 0; f < 8; ++f)
#pragma unroll
        for (int c = 0; c < 4; ++c) oacc[f][c] = 0.f;

    const bf16* khp = g_kh + headbase;
    const bf16* klp = g_kl + headbase;
    const bf16* vhp = g_vh + headbase;
    const bf16* vlp = g_vl + headbase;

    auto issue_kv = [&](int kt) {
        const int k0 = kt * 64;
        const uint32_t stg = sb + AKV_BASE + (kt & 1) * (4 * AKTILE);
        const bf16* srcs[4] = { khp + (size_t)k0 * HDIM, klp + (size_t)k0 * HDIM,
                                vhp + (size_t)k0 * HDIM, vlp + (size_t)k0 * HDIM };
#pragma unroll
        for (int i = 0; i < 8; ++i) {
            int s = tid + 256 * i;
            int t = s >> 9;
            int local = s & 511;
            int row = local >> 3, s8 = local & 7;
            cp16(stg + t * AKTILE + row * APITCH + s8 * 16,
                 srcs[t] + (size_t)row * HDIM + s8 * 8);
        }
        CP_COMMIT();
    };

    const int last = 2 * qt + 1;
    issue_kv(0);
    for (int kt = 0; kt <= last; ++kt) {
        if (kt < last) { issue_kv(kt + 1); CP_WAIT1(); } else { CP_WAIT0(); }
        __syncthreads();
        const uint32_t stg = sb + AKV_BASE + (kt & 1) * (4 * AKTILE);

        // ---- S = q.k^T ----
        float sacc[8][4];
#pragma unroll
        for (int f = 0; f < 8; ++f)
#pragma unroll
            for (int c = 0; c < 4; ++c) sacc[f][c] = 0.f;

#pragma unroll
        for (int ks = 0; ks < 4; ++ks) {
            const int kb = ks * 32;
            uint32_t qh4[4], ql4[4];
            ldsm4(qh4, lane_addr(sb + 0 * AQTILE + (16 * wid) * APITCH + kb, lane, APITCH));
            ldsm4(ql4, lane_addr(sb + 1 * AQTILE + (16 * wid) * APITCH + kb, lane, APITCH));
#pragma unroll
            for (int jf = 0; jf < 4; ++jf) {
                uint32_t kh4[4], kl4[4];
                ldsm4(kh4, lane_addr(stg + 0 * AKTILE + (16 * jf) * APITCH + kb, lane, APITCH));
                ldsm4(kl4, lane_addr(stg + 1 * AKTILE + (16 * jf) * APITCH + kb, lane, APITCH));
                mma_bf16(sacc[2 * jf],     qh4, kh4[0], kh4[2]);
                mma_bf16(sacc[2 * jf + 1], qh4, kh4[1], kh4[3]);
                mma_bf16(sacc[2 * jf],     qh4, kl4[0], kl4[2]);
                mma_bf16(sacc[2 * jf + 1], qh4, kl4[1], kl4[3]);
                mma_bf16(sacc[2 * jf],     ql4, kh4[0], kh4[2]);
                mma_bf16(sacc[2 * jf + 1], ql4, kh4[1], kh4[3]);
            }
        }

        // ---- decay + causal ----
        const int distbase = q0 - kt * 64;   // can be -64 on the last tile
#pragma unroll
        for (int f = 0; f < 8; ++f) {
#pragma unroll
            for (int c = 0; c < 4; ++c) {
                int j = 8 * f + 2 * qlane + (c & 1);
                int i = 16 * wid + quad + ((c >> 1) << 3);
                int idx = distbase + i - j;
                float w = (idx >= 0) ? spg[idx] : 0.f;
                sacc[f][c] *= w;
            }
        }

        // ---- pack P ----
        uint32_t phi[4][4], plo[4][4];
#pragma unroll
        for (int s = 0; s < 4; ++s) {
            split2(sacc[2 * s][0],     sacc[2 * s][1],     phi[s][0], plo[s][0]);
            split2(sacc[2 * s][2],     sacc[2 * s][3],     phi[s][1], plo[s][1]);
            split2(sacc[2 * s + 1][0], sacc[2 * s + 1][1], phi[s][2], plo[s][2]);
            split2(sacc[2 * s + 1][2], sacc[2 * s + 1][3], phi[s][3], plo[s][3]);
        }

        // ---- O += P.v ----
#pragma unroll
        for (int s = 0; s < 4; ++s) {
#pragma unroll
            for (int g = 0; g < 4; ++g) {
                uint32_t vh4[4], vl4[4];
                ldsm4t(vh4, lane_addr(stg + 2 * AKTILE + (16 * s) * APITCH + g * 32, lane, APITCH));
                ldsm4t(vl4, lane_addr(stg + 3 * AKTILE + (16 * s) * APITCH + g * 32, lane, APITCH));
                mma_bf16(oacc[2 * g],     phi[s], vh4[0], vh4[1]);
                mma_bf16(oacc[2 * g + 1], phi[s], vh4[2], vh4[3]);
                mma_bf16(oacc[2 * g],     phi[s], vl4[0], vl4[1]);
                mma_bf16(oacc[2 * g + 1], phi[s], vl4[2], vl4[3]);
                mma_bf16(oacc[2 * g],     plo[s], vh4[0], vh4[1]);
                mma_bf16(oacc[2 * g + 1], plo[s], vh4[2], vh4[3]);
            }
        }
        __syncthreads();
    }

    // ---- groupnorm via quad shuffles ----
    float sA = 0.f, sB = 0.f;
#pragma unroll
    for (int f = 0; f < 8; ++f) { sA += oacc[f][0] + oacc[f][1]; sB += oacc[f][2] + oacc[f][3]; }
    sA += __shfl_xor_sync(0xFFFFFFFFu, sA, 1); sA += __shfl_xor_sync(0xFFFFFFFFu, sA, 2);
    sB += __shfl_xor_sync(0xFFFFFFFFu, sB, 1); sB += __shfl_xor_sync(0xFFFFFFFFu, sB, 2);
    float mA = sA * (1.f / 64.f), mB = sB * (1.f / 64.f);
    float vA = 0.f, vB = 0.f;
#pragma unroll
    for (int f = 0; f < 8; ++f) {
        float d0 = oacc[f][0] - mA, d1 = oacc[f][1] - mA;
        float d2 = oacc[f][2] - mB, d3 = oacc[f][3] - mB;
        vA += d0 * d0 + d1 * d1;
        vB += d2 * d2 + d3 * d3;
    }
    vA += __shfl_xor_sync(0xFFFFFFFFu, vA, 1); vA += __shfl_xor_sync(0xFFFFFFFFu, vA, 2);
    vB += __shfl_xor_sync(0xFFFFFFFFu, vB, 1); vB += __shfl_xor_sync(0xFFFFFFFFu, vB, 2);
    float rA = rsqrtf(vA * (1.f / 64.f) + 1e-6f);
    float rB = rsqrtf(vB * (1.f / 64.f) + 1e-6f);

    // ---- gate + write hidden (bf16 hi/lo, B,N,E) ----
    const int iA = q0 + 16 * wid + quad;
    const int iB = iA + 8;
#pragma unroll
    for (int f = 0; f < 8; ++f) {
        int d = 8 * f + 2 * qlane;
        size_t eA = (size_t)(b * SEQ + iA) * EMB + h * HDIM + d;
        size_t eB = (size_t)(b * SEQ + iB) * EMB + h * HDIM + d;
        float2 gA = *(const float2*)(g_gate + eA);
        float2 gB = *(const float2*)(g_gate + eB);
        float x0 = (oacc[f][0] - mA) * rA * gA.x;
        float x1 = (oacc[f][1] - mA) * rA * gA.y;
        float y0 = (oacc[f][2] - mB) * rB * gB.x;
        float y1 = (oacc[f][3] - mB) * rB * gB.y;
        uint32_t uh, ul;
        split2(x0, x1, uh, ul);
        *(uint32_t*)(g_hh + eA) = uh;
        *(uint32_t*)(g_hl + eA) = ul;
        split2(y0, y1, uh, ul);
        *(uint32_t*)(g_hh + eB) = uh;
        *(uint32_t*)(g_hl + eB) = ul;
    }
}

// ---------------- launch ----------------
extern "C" void kernel_launch(void* const* d_in, const int* in_sizes, int n_in,
                              void* d_out, int out_size) {
    const float* query  = (const float*)d_in[0];
    const float* key_in = (const float*)d_in[1];
    const float* value  = (const float*)d_in[2];
    const float* Wq = (const float*)d_in[3];
    const float* bq = (const float*)d_in[4];
    const float* Wk = (const float*)d_in[5];
    const float* bk = (const float*)d_in[6];
    const float* Wv = (const float*)d_in[7];
    const float* bv = (const float*)d_in[8];
    const float* Wg = (const float*)d_in[9];
    const float* bg = (const float*)d_in[10];
    const float* Wo = (const float*)d_in[11];
    const float* bo = (const float*)d_in[12];
    float* out = (float*)d_out;

    float* gatep;
    cudaGetSymbolAddress((void**)&gatep, g_gate);

    bf16 *xqh,*xql,*xkh,*xkl,*xvh,*xvl,*hh,*hl;
    bf16 *wqh,*wql,*wkh,*wkl,*wvh,*wvl,*wgh,*wgl,*woh,*wol;
    bf16 *qh,*ql,*kh,*kl,*vh,*vl;
    cudaGetSymbolAddress((void**)&xqh, g_xqh); cudaGetSymbolAddress((void**)&xql, g_xql);
    cudaGetSymbolAddress((void**)&xkh, g_xkh); cudaGetSymbolAddress((void**)&xkl, g_xkl);
    cudaGetSymbolAddress((void**)&xvh, g_xvh); cudaGetSymbolAddress((void**)&xvl, g_xvl);
    cudaGetSymbolAddress((void**)&hh, g_hh);   cudaGetSymbolAddress((void**)&hl, g_hl);
    cudaGetSymbolAddress((void**)&wqh, g_wqh); cudaGetSymbolAddress((void**)&wql, g_wql);
    cudaGetSymbolAddress((void**)&wkh, g_wkh); cudaGetSymbolAddress((void**)&wkl, g_wkl);
    cudaGetSymbolAddress((void**)&wvh, g_wvh); cudaGetSymbolAddress((void**)&wvl, g_wvl);
    cudaGetSymbolAddress((void**)&wgh, g_wgh); cudaGetSymbolAddress((void**)&wgl, g_wgl);
    cudaGetSymbolAddress((void**)&woh, g_woh); cudaGetSymbolAddress((void**)&wol, g_wol);
    cudaGetSymbolAddress((void**)&qh, g_qh);   cudaGetSymbolAddress((void**)&ql, g_ql);
    cudaGetSymbolAddress((void**)&kh, g_kh);   cudaGetSymbolAddress((void**)&kl, g_kl);
    cudaGetSymbolAddress((void**)&vh, g_vh);   cudaGetSymbolAddress((void**)&vl, g_vl);

    cudaFuncSetAttribute(gemm_mma<0>, cudaFuncAttributeMaxDynamicSharedMemorySize, GSMEM);
    cudaFuncSetAttribute(gemm_mma<1>, cudaFuncAttributeMaxDynamicSharedMemorySize, GSMEM);
    cudaFuncSetAttribute(gemm_mma<2>, cudaFuncAttributeMaxDynamicSharedMemorySize, GSMEM);
    cudaFuncSetAttribute(gemm_mma<3>, cudaFuncAttributeMaxDynamicSharedMemorySize, GSMEM);
    cudaFuncSetAttribute(gemm_mma<4>, cudaFuncAttributeMaxDynamicSharedMemorySize, GSMEM);
    cudaFuncSetAttribute(attention_mma, cudaFuncAttributeMaxDynamicSharedMemorySize, AT_SMEM);

    init_tables<<<256, 256>>>();

    const int NA4 = MROWS * EMB / 4;
    const int NW4 = EMB * EMB / 4;
    convert_pair4<<<(NA4 + 255) / 256, 256>>>((const float4*)query,  (uint2*)xqh, (uint2*)xql, NA4);
    convert_pair4<<<(NA4 + 255) / 256, 256>>>((const float4*)key_in, (uint2*)xkh, (uint2*)xkl, NA4);
    convert_pair4<<<(NA4 + 255) / 256, 256>>>((const float4*)value,  (uint2*)xvh, (uint2*)xvl, NA4);
    convert_pair4<<<(NW4 + 255) / 256, 256>>>((const float4*)Wq, (uint2*)wqh, (uint2*)wql, NW4);
    convert_pair4<<<(NW4 + 255) / 256, 256>>>((const float4*)Wk, (uint2*)wkh, (uint2*)wkl, NW4);
    convert_pair4<<<(NW4 + 255) / 256, 256>>>((const float4*)Wv, (uint2*)wvh, (uint2*)wvl, NW4);
    convert_pair4<<<(NW4 + 255) / 256, 256>>>((const float4*)Wg, (uint2*)wgh, (uint2*)wgl, NW4);
    convert_pair4<<<(NW4 + 255) / 256, 256>>>((const float4*)Wo, (uint2*)woh, (uint2*)wol, NW4);

    dim3 gg(EMB / 128, MROWS / 128);   // (8, 32)
    gemm_mma<1><<<gg, 256, GSMEM>>>(xqh, xql, wqh, wql, bq, nullptr, qh, ql);
    gemm_mma<2><<<gg, 256, GSMEM>>>(xkh, xkl, wkh, wkl, bk, nullptr, kh, kl);
    gemm_mma<3><<<gg, 256, GSMEM>>>(xvh, xvl, wvh, wvl, bv, nullptr, vh, vl);
    gemm_mma<4><<<gg, 256, GSMEM>>>(xqh, xql, wgh, wgl, bg, gatep, nullptr, nullptr);

    attention_mma<<<dim3(SEQ / 128, HEADS, BATCH), 256, AT_SMEM>>>();

    gemm_mma<0><<<gg, 256, GSMEM>>>(hh, hl, woh, wol, bo, out, nullptr, nullptr);
}

// round 6
// speedup vs baseline: 2.2003x; 1.0428x over previous
#include <cuda_runtime.h>
#include <cuda_bf16.h>
#include <math.h>
#include <stdint.h>

#define BATCH 2
#define SEQ   2048
#define EMB   1024
#define HEADS 16
#define HDIM  64
#define NPAIR 32
#define MROWS (BATCH*SEQ)   // 4096

typedef __nv_bfloat16 bf16;

// ---------------- scratch (device globals; no allocation allowed) ----------------
__device__ float g_gate[BATCH*SEQ*EMB];
__device__ float g_sin[SEQ*NPAIR];
__device__ float g_cos[SEQ*NPAIR];
__device__ float g_gpow[HEADS*SEQ];

__device__ __align__(16) bf16 g_xqh[MROWS*EMB], g_xql[MROWS*EMB];
__device__ __align__(16) bf16 g_xkh[MROWS*EMB], g_xkl[MROWS*EMB];
__device__ __align__(16) bf16 g_xvh[MROWS*EMB], g_xvl[MROWS*EMB];
__device__ __align__(16) bf16 g_hh [MROWS*EMB], g_hl [MROWS*EMB];
__device__ __align__(16) bf16 g_wqh[EMB*EMB], g_wql[EMB*EMB];
__device__ __align__(16) bf16 g_wkh[EMB*EMB], g_wkl[EMB*EMB];
__device__ __align__(16) bf16 g_wvh[EMB*EMB], g_wvl[EMB*EMB];
__device__ __align__(16) bf16 g_wgh[EMB*EMB], g_wgl[EMB*EMB];
__device__ __align__(16) bf16 g_woh[EMB*EMB], g_wol[EMB*EMB];
__device__ __align__(16) bf16 g_qh[MROWS*EMB], g_ql[MROWS*EMB];
__device__ __align__(16) bf16 g_kh[MROWS*EMB], g_kl[MROWS*EMB];
__device__ __align__(16) bf16 g_vh[MROWS*EMB], g_vl[MROWS*EMB];

// ---------------- helpers ----------------
__device__ __forceinline__ uint32_t smem_u32(const void* p) {
    uint32_t a;
    asm("{ .reg .u64 t; cvta.to.shared.u64 t, %1; cvt.u32.u64 %0, t; }" : "=r"(a) : "l"(p));
    return a;
}
__device__ __forceinline__ void cp16(uint32_t dst, const void* src) {
    asm volatile("cp.async.cg.shared.global [%0], [%1], 16;" :: "r"(dst), "l"(src));
}
#define CP_COMMIT() asm volatile("cp.async.commit_group;" ::: "memory")
#define CP_WAIT0()  asm volatile("cp.async.wait_group 0;" ::: "memory")
#define CP_WAIT1()  asm volatile("cp.async.wait_group 1;" ::: "memory")

__device__ __forceinline__ void ldsm4(uint32_t* r, uint32_t addr) {
    asm volatile("ldmatrix.sync.aligned.m8n8.x4.shared.b16 {%0,%1,%2,%3}, [%4];"
                 : "=r"(r[0]), "=r"(r[1]), "=r"(r[2]), "=r"(r[3]) : "r"(addr));
}
__device__ __forceinline__ void ldsm4t(uint32_t* r, uint32_t addr) {
    asm volatile("ldmatrix.sync.aligned.m8n8.x4.trans.shared.b16 {%0,%1,%2,%3}, [%4];"
                 : "=r"(r[0]), "=r"(r[1]), "=r"(r[2]), "=r"(r[3]) : "r"(addr));
}
// group g=lane>>3: row = r0 + (lane&7) + 8*(g&1); colByte += 16*(g>>1)
__device__ __forceinline__ uint32_t lane_addr(uint32_t base, int lane, int pitch) {
    int g = lane >> 3;
    int row = (lane & 7) + ((g & 1) << 3);
    return base + row * pitch + ((g >> 1) << 4);
}
__device__ __forceinline__ void mma_bf16(float* d, const uint32_t* a, uint32_t b0, uint32_t b1) {
    asm volatile(
        "mma.sync.aligned.m16n8k16.row.col.f32.bf16.bf16.f32 "
        "{%0,%1,%2,%3}, {%4,%5,%6,%7}, {%8,%9}, {%0,%1,%2,%3};"
        : "+f"(d[0]), "+f"(d[1]), "+f"(d[2]), "+f"(d[3])
        : "r"(a[0]), "r"(a[1]), "r"(a[2]), "r"(a[3]), "r"(b0), "r"(b1));
}
__device__ __forceinline__ uint32_t pack2(float lo, float hi) {
    uint32_t r;
    asm("cvt.rn.bf16x2.f32 %0, %1, %2;" : "=r"(r) : "f"(hi), "f"(lo));
    return r;
}
__device__ __forceinline__ void split2(float v0, float v1, uint32_t& hi, uint32_t& lo) {
    float h0 = __bfloat162float(__float2bfloat16_rn(v0));
    float h1 = __bfloat162float(__float2bfloat16_rn(v1));
    hi = pack2(h0, h1);
    lo = pack2(v0 - h0, v1 - h1);
}

// ---------------- table init ----------------
__global__ void init_tables() {
    int tid = blockIdx.x * blockDim.x + threadIdx.x;
    if (tid < SEQ * NPAIR) {
        int n = tid / NPAIR, p = tid % NPAIR;
        float x = (float)p / 31.0f;
        float theta = (float)exp(-(double)x * 9.210340371976184);
        float ang = (float)n * theta;
        g_sin[tid] = (float)sin((double)ang);
        g_cos[tid] = (float)cos((double)ang);
    }
    if (tid < HEADS * SEQ) {
        int h = tid / SEQ, dist = tid % SEQ;
        double t = (double)h / 15.0;
        float l = (float)((1.0 - t) * (-3.4657359027997265) + t * (-6.238324625039508));
        float gamma = 1.0f - expf(l);
        g_gpow[tid] = (float)exp((double)dist * log((double)gamma));
    }
}

// ---------------- fused fp32 -> bf16 hi/lo splits (8 jobs, 1 launch) ----------------
struct ConvJob { const float4* src; uint2* hi; uint2* lo; int n4; };
struct ConvArgs { ConvJob j[8]; };

__global__ void convert_all(ConvArgs a) {
    const ConvJob jb = a.j[blockIdx.y];
    int i = blockIdx.x * blockDim.x + threadIdx.x;
    if (i < jb.n4) {
        float4 x = jb.src[i];
        uint32_t h0, l0, h1, l1;
        split2(x.x, x.y, h0, l0);
        split2(x.z, x.w, h1, l1);
        jb.hi[i] = make_uint2(h0, h1);
        jb.lo[i] = make_uint2(l0, l1);
    }
}

// ---------------- mma.sync GEMM ----------------
#define GPITCH 80
#define GTILE  (128*GPITCH)
#define GSTAGE (4*GTILE)
#define GSMEM  (2*GSTAGE)

template<int MODE>
__global__ __launch_bounds__(256, 2) void gemm_mma(
        const bf16* __restrict__ Ah, const bf16* __restrict__ Al,
        const bf16* __restrict__ Wh, const bf16* __restrict__ Wl,
        const float* __restrict__ bias,
        float* __restrict__ Cf, bf16* __restrict__ Chi, bf16* __restrict__ Clo) {
    extern __shared__ char sm[];
    const uint32_t sb = smem_u32(sm);
    const int tid = threadIdx.x;
    const int lane = tid & 31, wid = tid >> 5;
    const int warpM = wid & 3, warpN = wid >> 2;
    const int m0 = blockIdx.y * 128, j0 = blockIdx.x * 128;

    const bf16* srcs[4] = { Ah + (size_t)m0 * EMB, Al + (size_t)m0 * EMB,
                            Wh + (size_t)j0 * EMB, Wl + (size_t)j0 * EMB };

    auto issue = [&](int c) {
        const int k0 = c * 32;
        const uint32_t stg = sb + (c & 1) * GSTAGE;
#pragma unroll
        for (int i = 0; i < 8; ++i) {
            int s = tid + 256 * i;
            int t = s >> 9;
            int local = s & 511;
            int row = local >> 2, s4 = local & 3;
            cp16(stg + t * GTILE + row * GPITCH + s4 * 16,
                 srcs[t] + (size_t)row * EMB + k0 + s4 * 8);
        }
        CP_COMMIT();
    };

    float acc[2][8][4];
#pragma unroll
    for (int a = 0; a < 2; ++a)
#pragma unroll
        for (int b = 0; b < 8; ++b)
#pragma unroll
            for (int c = 0; c < 4; ++c) acc[a][b][c] = 0.f;

    issue(0);
    for (int c = 0; c < 32; ++c) {
        if (c < 31) { issue(c + 1); CP_WAIT1(); } else { CP_WAIT0(); }
        __syncthreads();
        const uint32_t st = sb + (c & 1) * GSTAGE;
#pragma unroll
        for (int ks = 0; ks < 2; ++ks) {
            const int kb = ks * 32;
            uint32_t ah[2][4], al[2][4], bb[4][4];
#pragma unroll
            for (int mf = 0; mf < 2; ++mf) {
                uint32_t rbase = st + (32 * warpM + 16 * mf) * GPITCH + kb;
                ldsm4(ah[mf], lane_addr(rbase, lane, GPITCH));
                ldsm4(al[mf], lane_addr(rbase + GTILE, lane, GPITCH));
            }
#pragma unroll
            for (int nf = 0; nf < 4; ++nf)
                ldsm4(bb[nf], lane_addr(st + 2 * GTILE + (64 * warpN + 16 * nf) * GPITCH + kb, lane, GPITCH));
            // pass 1: Ah x Wh  (acc reuse distance = 16)
#pragma unroll
            for (int mf = 0; mf < 2; ++mf)
#pragma unroll
                for (int nf = 0; nf < 4; ++nf) {
                    mma_bf16(acc[mf][2 * nf],     ah[mf], bb[nf][0], bb[nf][2]);
                    mma_bf16(acc[mf][2 * nf + 1], ah[mf], bb[nf][1], bb[nf][3]);
                }
            // pass 2: Al x Wh
#pragma unroll
            for (int mf = 0; mf < 2; ++mf)
#pragma unroll
                for (int nf = 0; nf < 4; ++nf) {
                    mma_bf16(acc[mf][2 * nf],     al[mf], bb[nf][0], bb[nf][2]);
                    mma_bf16(acc[mf][2 * nf + 1], al[mf], bb[nf][1], bb[nf][3]);
                }
            // pass 3: Ah x Wl
#pragma unroll
            for (int nf = 0; nf < 4; ++nf)
                ldsm4(bb[nf], lane_addr(st + 3 * GTILE + (64 * warpN + 16 * nf) * GPITCH + kb, lane, GPITCH));
#pragma unroll
            for (int mf = 0; mf < 2; ++mf)
#pragma unroll
                for (int nf = 0; nf < 4; ++nf) {
                    mma_bf16(acc[mf][2 * nf],     ah[mf], bb[nf][0], bb[nf][2]);
                    mma_bf16(acc[mf][2 * nf + 1], ah[mf], bb[nf][1], bb[nf][3]);
                }
        }
        __syncthreads();
    }

    const int quad = lane >> 2, qlane = lane & 3;
#pragma unroll
    for (int mf = 0; mf < 2; ++mf) {
#pragma unroll
        for (int half = 0; half < 2; ++half) {
            int r = 32 * warpM + 16 * mf + quad + half * 8;
            int m = m0 + r;
            int bb_ = m >> 11, n = m & (SEQ - 1);
#pragma unroll
            for (int nf = 0; nf < 8; ++nf) {
                int col = j0 + 64 * warpN + 8 * nf + 2 * qlane;
                float v0 = acc[mf][nf][half * 2 + 0] + __ldg(bias + col);
                float v1 = acc[mf][nf][half * 2 + 1] + __ldg(bias + col + 1);
                if (MODE == 1 || MODE == 2) {
                    int p = (col & 63) >> 1;
                    float s = g_sin[n * NPAIR + p], cs = g_cos[n * NPAIR + p];
                    float t0 = v0 * cs - v1 * s;
                    float t1 = v1 * cs + v0 * s;
                    v0 = t0; v1 = t1;
                    if (MODE == 2) { v0 *= 0.125f; v1 *= 0.125f; }
                }
                if (MODE == 4) {
                    v0 = v0 / (1.f + expf(-v0));
                    v1 = v1 / (1.f + expf(-v1));
                }
                if (MODE == 0 || MODE == 4) {
                    *(float2*)(Cf + (size_t)(bb_ * SEQ + n) * EMB + col) = make_float2(v0, v1);
                } else {
                    int hh_ = col >> 6, d = col & 63;
                    size_t idx = ((size_t)((bb_ * HEADS + hh_) * SEQ + n)) * HDIM + d;
                    uint32_t uh, ul;
                    split2(v0, v1, uh, ul);
                    *(uint32_t*)(Chi + idx) = uh;
                    *(uint32_t*)(Clo + idx) = ul;
                }
            }
        }
    }
}

// ---------------- retention attention: 256 threads, q-tile 128, 2-stage kv ----------------
#define APITCH 144               // 64 bf16 (128B) + 16B pad
#define AKTILE (64*APITCH)       // 9216
#define AQTILE (128*APITCH)      // 18432
#define AKV_BASE (2*AQTILE)      // 36864
#define AGP_BASE (AKV_BASE + 2*4*AKTILE)   // 110592
#define AT_SMEM  (AGP_BASE + SEQ*4)        // 118784

__global__ __launch_bounds__(256) void attention_mma() {
    extern __shared__ char sm[];
    const uint32_t sb = smem_u32(sm);
    float* spg = (float*)(sm + AGP_BASE);

    const int tid = threadIdx.x;
    const int lane = tid & 31, wid = tid >> 5;          // wid 0..7
    const int quad = lane >> 2, qlane = lane & 3;
    const int qt = (SEQ / 128 - 1) - blockIdx.x;        // heavy blocks first
    const int h = blockIdx.y, b = blockIdx.z;
    const int q0 = qt * 128;
    const size_t headbase = (size_t)(b * HEADS + h) * SEQ * HDIM;

    // stage q (hi/lo) + gp
    {
        const bf16* qhp = g_qh + headbase + (size_t)q0 * HDIM;
        const bf16* qlp = g_ql + headbase + (size_t)q0 * HDIM;
#pragma unroll
        for (int i = 0; i < 8; ++i) {
            int s = tid + 256 * i;
            int t = s >> 10;
            int local = s & 1023;
            int row = local >> 3, s8 = local & 7;
            cp16(sb + t * AQTILE + row * APITCH + s8 * 16,
                 (t ? qlp : qhp) + (size_t)row * HDIM + s8 * 8);
        }
#pragma unroll
        for (int i = 0; i < 2; ++i) {
            int s = tid + 256 * i;
            cp16(sb + AGP_BASE + s * 16, g_gpow + h * SEQ + s * 4);
        }
        CP_COMMIT();
    }

    float oacc[8][4];
#pragma unroll
    for (int f = 0; f < 8; ++f)
#pragma unroll
        for (int c = 0; c < 4; ++c) oacc[f][c] = 0.f;

    const bf16* khp = g_kh + headbase;
    const bf16* klp = g_kl + headbase;
    const bf16* vhp = g_vh + headbase;
    const bf16* vlp = g_vl + headbase;

    auto issue_kv = [&](int kt) {
        const int k0 = kt * 64;
        const uint32_t stg = sb + AKV_BASE + (kt & 1) * (4 * AKTILE);
        const bf16* srcs[4] = { khp + (size_t)k0 * HDIM, klp + (size_t)k0 * HDIM,
                                vhp + (size_t)k0 * HDIM, vlp + (size_t)k0 * HDIM };
#pragma unroll
        for (int i = 0; i < 8; ++i) {
            int s = tid + 256 * i;
            int t = s >> 9;
            int local = s & 511;
            int row = local >> 3, s8 = local & 7;
            cp16(stg + t * AKTILE + row * APITCH + s8 * 16,
                 srcs[t] + (size_t)row * HDIM + s8 * 8);
        }
        CP_COMMIT();
    };

    const int last = 2 * qt + 1;
    issue_kv(0);
    for (int kt = 0; kt <= last; ++kt) {
        if (kt < last) { issue_kv(kt + 1); CP_WAIT1(); } else { CP_WAIT0(); }
        __syncthreads();
        const uint32_t stg = sb + AKV_BASE + (kt & 1) * (4 * AKTILE);

        // ---- S = q.k^T (3 ordered passes, acc reuse distance 8) ----
        float sacc[8][4];
#pragma unroll
        for (int f = 0; f < 8; ++f)
#pragma unroll
            for (int c = 0; c < 4; ++c) sacc[f][c] = 0.f;

#pragma unroll
        for (int ks = 0; ks < 4; ++ks) {
            const int kb = ks * 32;
            uint32_t qh4[4], ql4[4], kh4[4][4], kl4[4][4];
            ldsm4(qh4, lane_addr(sb + 0 * AQTILE + (16 * wid) * APITCH + kb, lane, APITCH));
            ldsm4(ql4, lane_addr(sb + 1 * AQTILE + (16 * wid) * APITCH + kb, lane, APITCH));
#pragma unroll
            for (int jf = 0; jf < 4; ++jf) {
                ldsm4(kh4[jf], lane_addr(stg + 0 * AKTILE + (16 * jf) * APITCH + kb, lane, APITCH));
                ldsm4(kl4[jf], lane_addr(stg + 1 * AKTILE + (16 * jf) * APITCH + kb, lane, APITCH));
            }
#pragma unroll
            for (int jf = 0; jf < 4; ++jf) {
                mma_bf16(sacc[2 * jf],     qh4, kh4[jf][0], kh4[jf][2]);
                mma_bf16(sacc[2 * jf + 1], qh4, kh4[jf][1], kh4[jf][3]);
            }
#pragma unroll
            for (int jf = 0; jf < 4; ++jf) {
                mma_bf16(sacc[2 * jf],     qh4, kl4[jf][0], kl4[jf][2]);
                mma_bf16(sacc[2 * jf + 1], qh4, kl4[jf][1], kl4[jf][3]);
            }
#pragma unroll
            for (int jf = 0; jf < 4; ++jf) {
                mma_bf16(sacc[2 * jf],     ql4, kh4[jf][0], kh4[jf][2]);
                mma_bf16(sacc[2 * jf + 1], ql4, kh4[jf][1], kh4[jf][3]);
            }
        }

        // ---- decay + causal ----
        const int distbase = q0 - kt * 64;
#pragma unroll
        for (int f = 0; f < 8; ++f) {
#pragma unroll
            for (int c = 0; c < 4; ++c) {
                int j = 8 * f + 2 * qlane + (c & 1);
                int i = 16 * wid + quad + ((c >> 1) << 3);
                int idx = distbase + i - j;
                float w = (idx >= 0) ? spg[idx] : 0.f;
                sacc[f][c] *= w;
            }
        }

        // ---- pack P ----
        uint32_t phi[4][4], plo[4][4];
#pragma unroll
        for (int s = 0; s < 4; ++s) {
            split2(sacc[2 * s][0],     sacc[2 * s][1],     phi[s][0], plo[s][0]);
            split2(sacc[2 * s][2],     sacc[2 * s][3],     phi[s][1], plo[s][1]);
            split2(sacc[2 * s + 1][0], sacc[2 * s + 1][1], phi[s][2], plo[s][2]);
            split2(sacc[2 * s + 1][2], sacc[2 * s + 1][3], phi[s][3], plo[s][3]);
        }

        // ---- O += P.v (3 ordered passes per s, acc reuse distance 8) ----
#pragma unroll
        for (int s = 0; s < 4; ++s) {
            uint32_t vh4[4][4], vl4[4][4];
#pragma unroll
            for (int g = 0; g < 4; ++g) {
                ldsm4t(vh4[g], lane_addr(stg + 2 * AKTILE + (16 * s) * APITCH + g * 32, lane, APITCH));
                ldsm4t(vl4[g], lane_addr(stg + 3 * AKTILE + (16 * s) * APITCH + g * 32, lane, APITCH));
            }
#pragma unroll
            for (int g = 0; g < 4; ++g) {
                mma_bf16(oacc[2 * g],     phi[s], vh4[g][0], vh4[g][1]);
                mma_bf16(oacc[2 * g + 1], phi[s], vh4[g][2], vh4[g][3]);
            }
#pragma unroll
            for (int g = 0; g < 4; ++g) {
                mma_bf16(oacc[2 * g],     phi[s], vl4[g][0], vl4[g][1]);
                mma_bf16(oacc[2 * g + 1], phi[s], vl4[g][2], vl4[g][3]);
            }
#pragma unroll
            for (int g = 0; g < 4; ++g) {
                mma_bf16(oacc[2 * g],     plo[s], vh4[g][0], vh4[g][1]);
                mma_bf16(oacc[2 * g + 1], plo[s], vh4[g][2], vh4[g][3]);
            }
        }
        __syncthreads();
    }

    // ---- groupnorm via quad shuffles ----
    float sA = 0.f, sB = 0.f;
#pragma unroll
    for (int f = 0; f < 8; ++f) { sA += oacc[f][0] + oacc[f][1]; sB += oacc[f][2] + oacc[f][3]; }
    sA += __shfl_xor_sync(0xFFFFFFFFu, sA, 1); sA += __shfl_xor_sync(0xFFFFFFFFu, sA, 2);
    sB += __shfl_xor_sync(0xFFFFFFFFu, sB, 1); sB += __shfl_xor_sync(0xFFFFFFFFu, sB, 2);
    float mA = sA * (1.f / 64.f), mB = sB * (1.f / 64.f);
    float vA = 0.f, vB = 0.f;
#pragma unroll
    for (int f = 0; f < 8; ++f) {
        float d0 = oacc[f][0] - mA, d1 = oacc[f][1] - mA;
        float d2 = oacc[f][2] - mB, d3 = oacc[f][3] - mB;
        vA += d0 * d0 + d1 * d1;
        vB += d2 * d2 + d3 * d3;
    }
    vA += __shfl_xor_sync(0xFFFFFFFFu, vA, 1); vA += __shfl_xor_sync(0xFFFFFFFFu, vA, 2);
    vB += __shfl_xor_sync(0xFFFFFFFFu, vB, 1); vB += __shfl_xor_sync(0xFFFFFFFFu, vB, 2);
    float rA = rsqrtf(vA * (1.f / 64.f) + 1e-6f);
    float rB = rsqrtf(vB * (1.f / 64.f) + 1e-6f);

    // ---- gate + write hidden (bf16 hi/lo, B,N,E) ----
    const int iA = q0 + 16 * wid + quad;
    const int iB = iA + 8;
#pragma unroll
    for (int f = 0; f < 8; ++f) {
        int d = 8 * f + 2 * qlane;
        size_t eA = (size_t)(b * SEQ + iA) * EMB + h * HDIM + d;
        size_t eB = (size_t)(b * SEQ + iB) * EMB + h * HDIM + d;
        float2 gA = *(const float2*)(g_gate + eA);
        float2 gB = *(const float2*)(g_gate + eB);
        float x0 = (oacc[f][0] - mA) * rA * gA.x;
        float x1 = (oacc[f][1] - mA) * rA * gA.y;
        float y0 = (oacc[f][2] - mB) * rB * gB.x;
        float y1 = (oacc[f][3] - mB) * rB * gB.y;
        uint32_t uh, ul;
        split2(x0, x1, uh, ul);
        *(uint32_t*)(g_hh + eA) = uh;
        *(uint32_t*)(g_hl + eA) = ul;
        split2(y0, y1, uh, ul);
        *(uint32_t*)(g_hh + eB) = uh;
        *(uint32_t*)(g_hl + eB) = ul;
    }
}

// ---------------- launch ----------------
extern "C" void kernel_launch(void* const* d_in, const int* in_sizes, int n_in,
                              void* d_out, int out_size) {
    const float* query  = (const float*)d_in[0];
    const float* key_in = (const float*)d_in[1];
    const float* value  = (const float*)d_in[2];
    const float* Wq = (const float*)d_in[3];
    const float* bq = (const float*)d_in[4];
    const float* Wk = (const float*)d_in[5];
    const float* bk = (const float*)d_in[6];
    const float* Wv = (const float*)d_in[7];
    const float* bv = (const float*)d_in[8];
    const float* Wg = (const float*)d_in[9];
    const float* bg = (const float*)d_in[10];
    const float* Wo = (const float*)d_in[11];
    const float* bo = (const float*)d_in[12];
    float* out = (float*)d_out;

    float* gatep;
    cudaGetSymbolAddress((void**)&gatep, g_gate);

    bf16 *xqh,*xql,*xkh,*xkl,*xvh,*xvl,*hh,*hl;
    bf16 *wqh,*wql,*wkh,*wkl,*wvh,*wvl,*wgh,*wgl,*woh,*wol;
    bf16 *qh,*ql,*kh,*kl,*vh,*vl;
    cudaGetSymbolAddress((void**)&xqh, g_xqh); cudaGetSymbolAddress((void**)&xql, g_xql);
    cudaGetSymbolAddress((void**)&xkh, g_xkh); cudaGetSymbolAddress((void**)&xkl, g_xkl);
    cudaGetSymbolAddress((void**)&xvh, g_xvh); cudaGetSymbolAddress((void**)&xvl, g_xvl);
    cudaGetSymbolAddress((void**)&hh, g_hh);   cudaGetSymbolAddress((void**)&hl, g_hl);
    cudaGetSymbolAddress((void**)&wqh, g_wqh); cudaGetSymbolAddress((void**)&wql, g_wql);
    cudaGetSymbolAddress((void**)&wkh, g_wkh); cudaGetSymbolAddress((void**)&wkl, g_wkl);
    cudaGetSymbolAddress((void**)&wvh, g_wvh); cudaGetSymbolAddress((void**)&wvl, g_wvl);
    cudaGetSymbolAddress((void**)&wgh, g_wgh); cudaGetSymbolAddress((void**)&wgl, g_wgl);
    cudaGetSymbolAddress((void**)&woh, g_woh); cudaGetSymbolAddress((void**)&wol, g_wol);
    cudaGetSymbolAddress((void**)&qh, g_qh);   cudaGetSymbolAddress((void**)&ql, g_ql);
    cudaGetSymbolAddress((void**)&kh, g_kh);   cudaGetSymbolAddress((void**)&kl, g_kl);
    cudaGetSymbolAddress((void**)&vh, g_vh);   cudaGetSymbolAddress((void**)&vl, g_vl);

    cudaFuncSetAttribute(gemm_mma<0>, cudaFuncAttributeMaxDynamicSharedMemorySize, GSMEM);
    cudaFuncSetAttribute(gemm_mma<1>, cudaFuncAttributeMaxDynamicSharedMemorySize, GSMEM);
    cudaFuncSetAttribute(gemm_mma<2>, cudaFuncAttributeMaxDynamicSharedMemorySize, GSMEM);
    cudaFuncSetAttribute(gemm_mma<3>, cudaFuncAttributeMaxDynamicSharedMemorySize, GSMEM);
    cudaFuncSetAttribute(gemm_mma<4>, cudaFuncAttributeMaxDynamicSharedMemorySize, GSMEM);
    cudaFuncSetAttribute(attention_mma, cudaFuncAttributeMaxDynamicSharedMemorySize, AT_SMEM);

    init_tables<<<256, 256>>>();

    const int NA4 = MROWS * EMB / 4;   // 1048576
    const int NW4 = EMB * EMB / 4;     // 262144
    ConvArgs ca;
    ca.j[0] = { (const float4*)query,  (uint2*)xqh, (uint2*)xql, NA4 };
    ca.j[1] = { (const float4*)key_in, (uint2*)xkh, (uint2*)xkl, NA4 };
    ca.j[2] = { (const float4*)value,  (uint2*)xvh, (uint2*)xvl, NA4 };
    ca.j[3] = { (const float4*)Wq, (uint2*)wqh, (uint2*)wql, NW4 };
    ca.j[4] = { (const float4*)Wk, (uint2*)wkh, (uint2*)wkl, NW4 };
    ca.j[5] = { (const float4*)Wv, (uint2*)wvh, (uint2*)wvl, NW4 };
    ca.j[6] = { (const float4*)Wg, (uint2*)wgh, (uint2*)wgl, NW4 };
    ca.j[7] = { (const float4*)Wo, (uint2*)woh, (uint2*)wol, NW4 };
    convert_all<<<dim3((NA4 + 255) / 256, 8), 256>>>(ca);

    dim3 gg(EMB / 128, MROWS / 128);   // (8, 32)
    gemm_mma<1><<<gg, 256, GSMEM>>>(xqh, xql, wqh, wql, bq, nullptr, qh, ql);
    gemm_mma<2><<<gg, 256, GSMEM>>>(xkh, xkl, wkh, wkl, bk, nullptr, kh, kl);
    gemm_mma<3><<<gg, 256, GSMEM>>>(xvh, xvl, wvh, wvl, bv, nullptr, vh, vl);
    gemm_mma<4><<<gg, 256, GSMEM>>>(xqh, xql, wgh, wgl, bg, gatep, nullptr, nullptr);

    attention_mma<<<dim3(SEQ / 128, HEADS, BATCH), 256, AT_SMEM>>>();

    gemm_mma<0><<<gg, 256, GSMEM>>>(hh, hl, woh, wol, bo, out, nullptr, nullptr);
}

// round 7
// speedup vs baseline: 2.4626x; 1.1192x over previous
#include <cuda_runtime.h>
#include <cuda_bf16.h>
#include <math.h>
#include <stdint.h>

#define BATCH 2
#define SEQ   2048
#define EMB   1024
#define HEADS 16
#define HDIM  64
#define NPAIR 32
#define MROWS (BATCH*SEQ)   // 4096

typedef __nv_bfloat16 bf16;

// ---------------- scratch (device globals; no allocation allowed) ----------------
__device__ float g_gate[BATCH*SEQ*EMB];
__device__ float g_sin[SEQ*NPAIR];
__device__ float g_cos[SEQ*NPAIR];
__device__ float g_gpow[HEADS*SEQ];

__device__ __align__(16) bf16 g_xqh[MROWS*EMB], g_xql[MROWS*EMB];
__device__ __align__(16) bf16 g_xkh[MROWS*EMB], g_xkl[MROWS*EMB];
__device__ __align__(16) bf16 g_xvh[MROWS*EMB], g_xvl[MROWS*EMB];
__device__ __align__(16) bf16 g_hh [MROWS*EMB], g_hl [MROWS*EMB];
__device__ __align__(16) bf16 g_wqh[EMB*EMB], g_wql[EMB*EMB];
__device__ __align__(16) bf16 g_wkh[EMB*EMB], g_wkl[EMB*EMB];
__device__ __align__(16) bf16 g_wvh[EMB*EMB], g_wvl[EMB*EMB];
__device__ __align__(16) bf16 g_wgh[EMB*EMB], g_wgl[EMB*EMB];
__device__ __align__(16) bf16 g_woh[EMB*EMB], g_wol[EMB*EMB];
__device__ __align__(16) bf16 g_qh[MROWS*EMB], g_ql[MROWS*EMB];
__device__ __align__(16) bf16 g_kh[MROWS*EMB], g_kl[MROWS*EMB];
__device__ __align__(16) bf16 g_vh[MROWS*EMB], g_vl[MROWS*EMB];

// ---------------- helpers ----------------
__device__ __forceinline__ uint32_t smem_u32(const void* p) {
    uint32_t a;
    asm("{ .reg .u64 t; cvta.to.shared.u64 t, %1; cvt.u32.u64 %0, t; }" : "=r"(a) : "l"(p));
    return a;
}
__device__ __forceinline__ void cp16(uint32_t dst, const void* src) {
    asm volatile("cp.async.cg.shared.global [%0], [%1], 16;" :: "r"(dst), "l"(src));
}
#define CP_COMMIT() asm volatile("cp.async.commit_group;" ::: "memory")
#define CP_WAIT0()  asm volatile("cp.async.wait_group 0;" ::: "memory")

__device__ __forceinline__ void ldsm4(uint32_t* r, uint32_t addr) {
    asm volatile("ldmatrix.sync.aligned.m8n8.x4.shared.b16 {%0,%1,%2,%3}, [%4];"
                 : "=r"(r[0]), "=r"(r[1]), "=r"(r[2]), "=r"(r[3]) : "r"(addr));
}
__device__ __forceinline__ void ldsm4t(uint32_t* r, uint32_t addr) {
    asm volatile("ldmatrix.sync.aligned.m8n8.x4.trans.shared.b16 {%0,%1,%2,%3}, [%4];"
                 : "=r"(r[0]), "=r"(r[1]), "=r"(r[2]), "=r"(r[3]) : "r"(addr));
}
// group g=lane>>3: row = r0 + (lane&7) + 8*(g&1); colByte += 16*(g>>1)
__device__ __forceinline__ uint32_t lane_addr(uint32_t base, int lane, int pitch) {
    int g = lane >> 3;
    int row = (lane & 7) + ((g & 1) << 3);
    return base + row * pitch + ((g >> 1) << 4);
}
__device__ __forceinline__ void mma_bf16(float* d, const uint32_t* a, uint32_t b0, uint32_t b1) {
    asm volatile(
        "mma.sync.aligned.m16n8k16.row.col.f32.bf16.bf16.f32 "
        "{%0,%1,%2,%3}, {%4,%5,%6,%7}, {%8,%9}, {%0,%1,%2,%3};"
        : "+f"(d[0]), "+f"(d[1]), "+f"(d[2]), "+f"(d[3])
        : "r"(a[0]), "r"(a[1]), "r"(a[2]), "r"(a[3]), "r"(b0), "r"(b1));
}
__device__ __forceinline__ uint32_t pack2(float lo, float hi) {
    uint32_t r;
    asm("cvt.rn.bf16x2.f32 %0, %1, %2;" : "=r"(r) : "f"(hi), "f"(lo));
    return r;
}
__device__ __forceinline__ void split2(float v0, float v1, uint32_t& hi, uint32_t& lo) {
    float h0 = __bfloat162float(__float2bfloat16_rn(v0));
    float h1 = __bfloat162float(__float2bfloat16_rn(v1));
    hi = pack2(h0, h1);
    lo = pack2(v0 - h0, v1 - h1);
}

// ---------------- table init ----------------
__global__ void init_tables() {
    int tid = blockIdx.x * blockDim.x + threadIdx.x;
    if (tid < SEQ * NPAIR) {
        int n = tid / NPAIR, p = tid % NPAIR;
        float x = (float)p / 31.0f;
        float theta = (float)exp(-(double)x * 9.210340371976184);
        float ang = (float)n * theta;
        g_sin[tid] = (float)sin((double)ang);
        g_cos[tid] = (float)cos((double)ang);
    }
    if (tid < HEADS * SEQ) {
        int h = tid / SEQ, dist = tid % SEQ;
        double t = (double)h / 15.0;
        float l = (float)((1.0 - t) * (-3.4657359027997265) + t * (-6.238324625039508));
        float gamma = 1.0f - expf(l);
        g_gpow[tid] = (float)exp((double)dist * log((double)gamma));
    }
}

// ---------------- fused fp32 -> bf16 hi/lo splits ----------------
struct ConvJob { const float4* src; uint2* hi; uint2* lo; int n4; };
struct ConvArgs { ConvJob j[8]; };

__global__ void convert_all(ConvArgs a) {
    const ConvJob jb = a.j[blockIdx.y];
    int i = blockIdx.x * blockDim.x + threadIdx.x;
    if (i < jb.n4) {
        float4 x = jb.src[i];
        uint32_t h0, l0, h1, l1;
        split2(x.x, x.y, h0, l0);
        split2(x.z, x.w, h1, l1);
        jb.hi[i] = make_uint2(h0, h1);
        jb.lo[i] = make_uint2(l0, l1);
    }
}

// ---------------- mma.sync GEMM (multi-job, runtime mode) ----------------
// mode 0: plain f32 (B,N,E)    1: RoPE -> bf16 hi/lo (B,H,N,D)
// mode 2: RoPE/8 -> bf16 hi/lo 3: plain -> bf16 hi/lo 4: SiLU f32 (B,N,E)
#define GPITCH 80
#define GTILE  (128*GPITCH)
#define GSTAGE (4*GTILE)
#define GSMEM  (2*GSTAGE)

struct GemmJob {
    const bf16 *Ah, *Al, *Wh, *Wl;
    const float* bias;
    float* Cf; bf16 *Chi, *Clo;
    int mode;
};
struct GemmArgs { GemmJob j[4]; };

__global__ __launch_bounds__(256, 2) void gemm_mma(GemmArgs ga) {
    const GemmJob jb = ga.j[blockIdx.z];
    extern __shared__ char sm[];
    const uint32_t sb = smem_u32(sm);
    const int tid = threadIdx.x;
    const int lane = tid & 31, wid = tid >> 5;
    const int warpM = wid & 3, warpN = wid >> 2;
    const int m0 = blockIdx.y * 128, j0 = blockIdx.x * 128;

    const bf16* srcs[4] = { jb.Ah + (size_t)m0 * EMB, jb.Al + (size_t)m0 * EMB,
                            jb.Wh + (size_t)j0 * EMB, jb.Wl + (size_t)j0 * EMB };

    auto issue = [&](int c) {
        const int k0 = c * 32;
        const uint32_t stg = sb + (c & 1) * GSTAGE;
#pragma unroll
        for (int i = 0; i < 8; ++i) {
            int s = tid + 256 * i;
            int t = s >> 9;
            int local = s & 511;
            int row = local >> 2, s4 = local & 3;
            cp16(stg + t * GTILE + row * GPITCH + s4 * 16,
                 srcs[t] + (size_t)row * EMB + k0 + s4 * 8);
        }
        CP_COMMIT();
    };

    float acc[2][8][4];
#pragma unroll
    for (int a = 0; a < 2; ++a)
#pragma unroll
        for (int b = 0; b < 8; ++b)
#pragma unroll
            for (int c = 0; c < 4; ++c) acc[a][b][c] = 0.f;

    issue(0);
    for (int c = 0; c < 32; ++c) {
        CP_WAIT0();
        __syncthreads();
        if (c < 31) issue(c + 1);     // overlaps compute below
        const uint32_t st = sb + (c & 1) * GSTAGE;
#pragma unroll
        for (int ks = 0; ks < 2; ++ks) {
            const int kb = ks * 32;
            uint32_t ah[2][4], al[2][4], bb[4][4];
#pragma unroll
            for (int mf = 0; mf < 2; ++mf) {
                uint32_t rbase = st + (32 * warpM + 16 * mf) * GPITCH + kb;
                ldsm4(ah[mf], lane_addr(rbase, lane, GPITCH));
                ldsm4(al[mf], lane_addr(rbase + GTILE, lane, GPITCH));
            }
#pragma unroll
            for (int nf = 0; nf < 4; ++nf)
                ldsm4(bb[nf], lane_addr(st + 2 * GTILE + (64 * warpN + 16 * nf) * GPITCH + kb, lane, GPITCH));
            // pass 1: Ah x Wh
#pragma unroll
            for (int mf = 0; mf < 2; ++mf)
#pragma unroll
                for (int nf = 0; nf < 4; ++nf) {
                    mma_bf16(acc[mf][2 * nf],     ah[mf], bb[nf][0], bb[nf][2]);
                    mma_bf16(acc[mf][2 * nf + 1], ah[mf], bb[nf][1], bb[nf][3]);
                }
            // pass 2: Al x Wh
#pragma unroll
            for (int mf = 0; mf < 2; ++mf)
#pragma unroll
                for (int nf = 0; nf < 4; ++nf) {
                    mma_bf16(acc[mf][2 * nf],     al[mf], bb[nf][0], bb[nf][2]);
                    mma_bf16(acc[mf][2 * nf + 1], al[mf], bb[nf][1], bb[nf][3]);
                }
            // pass 3: Ah x Wl
#pragma unroll
            for (int nf = 0; nf < 4; ++nf)
                ldsm4(bb[nf], lane_addr(st + 3 * GTILE + (64 * warpN + 16 * nf) * GPITCH + kb, lane, GPITCH));
#pragma unroll
            for (int mf = 0; mf < 2; ++mf)
#pragma unroll
                for (int nf = 0; nf < 4; ++nf) {
                    mma_bf16(acc[mf][2 * nf],     ah[mf], bb[nf][0], bb[nf][2]);
                    mma_bf16(acc[mf][2 * nf + 1], ah[mf], bb[nf][1], bb[nf][3]);
                }
        }
    }

    const int mode = jb.mode;
    const int quad = lane >> 2, qlane = lane & 3;
#pragma unroll
    for (int mf = 0; mf < 2; ++mf) {
#pragma unroll
        for (int half = 0; half < 2; ++half) {
            int r = 32 * warpM + 16 * mf + quad + half * 8;
            int m = m0 + r;
            int bb_ = m >> 11, n = m & (SEQ - 1);
#pragma unroll
            for (int nf = 0; nf < 8; ++nf) {
                int col = j0 + 64 * warpN + 8 * nf + 2 * qlane;
                float v0 = acc[mf][nf][half * 2 + 0] + __ldg(jb.bias + col);
                float v1 = acc[mf][nf][half * 2 + 1] + __ldg(jb.bias + col + 1);
                if (mode == 1 || mode == 2) {
                    int p = (col & 63) >> 1;
                    float s = g_sin[n * NPAIR + p], cs = g_cos[n * NPAIR + p];
                    float t0 = v0 * cs - v1 * s;
                    float t1 = v1 * cs + v0 * s;
                    v0 = t0; v1 = t1;
                    if (mode == 2) { v0 *= 0.125f; v1 *= 0.125f; }
                }
                if (mode == 4) {
                    v0 = v0 / (1.f + expf(-v0));
                    v1 = v1 / (1.f + expf(-v1));
                }
                if (mode == 0 || mode == 4) {
                    *(float2*)(jb.Cf + (size_t)(bb_ * SEQ + n) * EMB + col) = make_float2(v0, v1);
                } else {
                    int hh_ = col >> 6, d = col & 63;
                    size_t idx = ((size_t)((bb_ * HEADS + hh_) * SEQ + n)) * HDIM + d;
                    uint32_t uh, ul;
                    split2(v0, v1, uh, ul);
                    *(uint32_t*)(jb.Chi + idx) = uh;
                    *(uint32_t*)(jb.Clo + idx) = ul;
                }
            }
        }
    }
}

// ---------------- retention attention: 256 threads, q-tile 128, 2-stage kv ----------------
#define APITCH 144               // 64 bf16 (128B) + 16B pad
#define AKTILE (64*APITCH)       // 9216
#define AQTILE (128*APITCH)      // 18432
#define AKV_BASE (2*AQTILE)      // 36864
#define AGP_BASE (AKV_BASE + 2*4*AKTILE)   // 110592
#define AT_SMEM  (AGP_BASE + SEQ*4)        // 118784

__global__ __launch_bounds__(256) void attention_mma() {
    extern __shared__ char sm[];
    const uint32_t sb = smem_u32(sm);
    float* spg = (float*)(sm + AGP_BASE);

    const int tid = threadIdx.x;
    const int lane = tid & 31, wid = tid >> 5;          // wid 0..7
    const int quad = lane >> 2, qlane = lane & 3;
    const int qt = (SEQ / 128 - 1) - blockIdx.x;        // heavy blocks first
    const int h = blockIdx.y, b = blockIdx.z;
    const int q0 = qt * 128;
    const size_t headbase = (size_t)(b * HEADS + h) * SEQ * HDIM;

    // stage q (hi/lo) + gp
    {
        const bf16* qhp = g_qh + headbase + (size_t)q0 * HDIM;
        const bf16* qlp = g_ql + headbase + (size_t)q0 * HDIM;
#pragma unroll
        for (int i = 0; i < 8; ++i) {
            int s = tid + 256 * i;
            int t = s >> 10;
            int local = s & 1023;
            int row = local >> 3, s8 = local & 7;
            cp16(sb + t * AQTILE + row * APITCH + s8 * 16,
                 (t ? qlp : qhp) + (size_t)row * HDIM + s8 * 8);
        }
#pragma unroll
        for (int i = 0; i < 2; ++i) {
            int s = tid + 256 * i;
            cp16(sb + AGP_BASE + s * 16, g_gpow + h * SEQ + s * 4);
        }
        CP_COMMIT();
    }

    float oacc[8][4];
#pragma unroll
    for (int f = 0; f < 8; ++f)
#pragma unroll
        for (int c = 0; c < 4; ++c) oacc[f][c] = 0.f;

    const bf16* khp = g_kh + headbase;
    const bf16* klp = g_kl + headbase;
    const bf16* vhp = g_vh + headbase;
    const bf16* vlp = g_vl + headbase;

    auto issue_kv = [&](int kt) {
        const int k0 = kt * 64;
        const uint32_t stg = sb + AKV_BASE + (kt & 1) * (4 * AKTILE);
        const bf16* srcs[4] = { khp + (size_t)k0 * HDIM, klp + (size_t)k0 * HDIM,
                                vhp + (size_t)k0 * HDIM, vlp + (size_t)k0 * HDIM };
#pragma unroll
        for (int i = 0; i < 8; ++i) {
            int s = tid + 256 * i;
            int t = s >> 9;
            int local = s & 511;
            int row = local >> 3, s8 = local & 7;
            cp16(stg + t * AKTILE + row * APITCH + s8 * 16,
                 srcs[t] + (size_t)row * HDIM + s8 * 8);
        }
        CP_COMMIT();
    };

    const int last = 2 * qt + 1;
    issue_kv(0);
    for (int kt = 0; kt <= last; ++kt) {
        CP_WAIT0();
        __syncthreads();
        if (kt < last) issue_kv(kt + 1);   // overlaps compute below
        const uint32_t stg = sb + AKV_BASE + (kt & 1) * (4 * AKTILE);

        // ---- S = q.k^T (3 ordered passes) ----
        float sacc[8][4];
#pragma unroll
        for (int f = 0; f < 8; ++f)
#pragma unroll
            for (int c = 0; c < 4; ++c) sacc[f][c] = 0.f;

#pragma unroll
        for (int ks = 0; ks < 4; ++ks) {
            const int kb = ks * 32;
            uint32_t qh4[4], ql4[4], kh4[4][4], kl4[4][4];
            ldsm4(qh4, lane_addr(sb + 0 * AQTILE + (16 * wid) * APITCH + kb, lane, APITCH));
            ldsm4(ql4, lane_addr(sb + 1 * AQTILE + (16 * wid) * APITCH + kb, lane, APITCH));
#pragma unroll
            for (int jf = 0; jf < 4; ++jf) {
                ldsm4(kh4[jf], lane_addr(stg + 0 * AKTILE + (16 * jf) * APITCH + kb, lane, APITCH));
                ldsm4(kl4[jf], lane_addr(stg + 1 * AKTILE + (16 * jf) * APITCH + kb, lane, APITCH));
            }
#pragma unroll
            for (int jf = 0; jf < 4; ++jf) {
                mma_bf16(sacc[2 * jf],     qh4, kh4[jf][0], kh4[jf][2]);
                mma_bf16(sacc[2 * jf + 1], qh4, kh4[jf][1], kh4[jf][3]);
            }
#pragma unroll
            for (int jf = 0; jf < 4; ++jf) {
                mma_bf16(sacc[2 * jf],     qh4, kl4[jf][0], kl4[jf][2]);
                mma_bf16(sacc[2 * jf + 1], qh4, kl4[jf][1], kl4[jf][3]);
            }
#pragma unroll
            for (int jf = 0; jf < 4; ++jf) {
                mma_bf16(sacc[2 * jf],     ql4, kh4[jf][0], kh4[jf][2]);
                mma_bf16(sacc[2 * jf + 1], ql4, kh4[jf][1], kh4[jf][3]);
            }
        }

        // ---- decay + causal ----
        const int distbase = q0 - kt * 64;
#pragma unroll
        for (int f = 0; f < 8; ++f) {
#pragma unroll
            for (int c = 0; c < 4; ++c) {
                int j = 8 * f + 2 * qlane + (c & 1);
                int i = 16 * wid + quad + ((c >> 1) << 3);
                int idx = distbase + i - j;
                float w = (idx >= 0) ? spg[idx] : 0.f;
                sacc[f][c] *= w;
            }
        }

        // ---- pack P ----
        uint32_t phi[4][4], plo[4][4];
#pragma unroll
        for (int s = 0; s < 4; ++s) {
            split2(sacc[2 * s][0],     sacc[2 * s][1],     phi[s][0], plo[s][0]);
            split2(sacc[2 * s][2],     sacc[2 * s][3],     phi[s][1], plo[s][1]);
            split2(sacc[2 * s + 1][0], sacc[2 * s + 1][1], phi[s][2], plo[s][2]);
            split2(sacc[2 * s + 1][2], sacc[2 * s + 1][3], phi[s][3], plo[s][3]);
        }

        // ---- O += P.v (3 ordered passes per s) ----
#pragma unroll
        for (int s = 0; s < 4; ++s) {
            uint32_t vh4[4][4], vl4[4][4];
#pragma unroll
            for (int g = 0; g < 4; ++g) {
                ldsm4t(vh4[g], lane_addr(stg + 2 * AKTILE + (16 * s) * APITCH + g * 32, lane, APITCH));
                ldsm4t(vl4[g], lane_addr(stg + 3 * AKTILE + (16 * s) * APITCH + g * 32, lane, APITCH));
            }
#pragma unroll
            for (int g = 0; g < 4; ++g) {
                mma_bf16(oacc[2 * g],     phi[s], vh4[g][0], vh4[g][1]);
                mma_bf16(oacc[2 * g + 1], phi[s], vh4[g][2], vh4[g][3]);
            }
#pragma unroll
            for (int g = 0; g < 4; ++g) {
                mma_bf16(oacc[2 * g],     phi[s], vl4[g][0], vl4[g][1]);
                mma_bf16(oacc[2 * g + 1], phi[s], vl4[g][2], vl4[g][3]);
            }
#pragma unroll
            for (int g = 0; g < 4; ++g) {
                mma_bf16(oacc[2 * g],     plo[s], vh4[g][0], vh4[g][1]);
                mma_bf16(oacc[2 * g + 1], plo[s], vh4[g][2], vh4[g][3]);
            }
        }
    }

    // ---- groupnorm via quad shuffles ----
    float sA = 0.f, sB = 0.f;
#pragma unroll
    for (int f = 0; f < 8; ++f) { sA += oacc[f][0] + oacc[f][1]; sB += oacc[f][2] + oacc[f][3]; }
    sA += __shfl_xor_sync(0xFFFFFFFFu, sA, 1); sA += __shfl_xor_sync(0xFFFFFFFFu, sA, 2);
    sB += __shfl_xor_sync(0xFFFFFFFFu, sB, 1); sB += __shfl_xor_sync(0xFFFFFFFFu, sB, 2);
    float mA = sA * (1.f / 64.f), mB = sB * (1.f / 64.f);
    float vA = 0.f, vB = 0.f;
#pragma unroll
    for (int f = 0; f < 8; ++f) {
        float d0 = oacc[f][0] - mA, d1 = oacc[f][1] - mA;
        float d2 = oacc[f][2] - mB, d3 = oacc[f][3] - mB;
        vA += d0 * d0 + d1 * d1;
        vB += d2 * d2 + d3 * d3;
    }
    vA += __shfl_xor_sync(0xFFFFFFFFu, vA, 1); vA += __shfl_xor_sync(0xFFFFFFFFu, vA, 2);
    vB += __shfl_xor_sync(0xFFFFFFFFu, vB, 1); vB += __shfl_xor_sync(0xFFFFFFFFu, vB, 2);
    float rA = rsqrtf(vA * (1.f / 64.f) + 1e-6f);
    float rB = rsqrtf(vB * (1.f / 64.f) + 1e-6f);

    // ---- gate + write hidden (bf16 hi/lo, B,N,E) ----
    const int iA = q0 + 16 * wid + quad;
    const int iB = iA + 8;
#pragma unroll
    for (int f = 0; f < 8; ++f) {
        int d = 8 * f + 2 * qlane;
        size_t eA = (size_t)(b * SEQ + iA) * EMB + h * HDIM + d;
        size_t eB = (size_t)(b * SEQ + iB) * EMB + h * HDIM + d;
        float2 gA = *(const float2*)(g_gate + eA);
        float2 gB = *(const float2*)(g_gate + eB);
        float x0 = (oacc[f][0] - mA) * rA * gA.x;
        float x1 = (oacc[f][1] - mA) * rA * gA.y;
        float y0 = (oacc[f][2] - mB) * rB * gB.x;
        float y1 = (oacc[f][3] - mB) * rB * gB.y;
        uint32_t uh, ul;
        split2(x0, x1, uh, ul);
        *(uint32_t*)(g_hh + eA) = uh;
        *(uint32_t*)(g_hl + eA) = ul;
        split2(y0, y1, uh, ul);
        *(uint32_t*)(g_hh + eB) = uh;
        *(uint32_t*)(g_hl + eB) = ul;
    }
}

// ---------------- launch ----------------
extern "C" void kernel_launch(void* const* d_in, const int* in_sizes, int n_in,
                              void* d_out, int out_size) {
    const float* query  = (const float*)d_in[0];
    const float* key_in = (const float*)d_in[1];
    const float* value  = (const float*)d_in[2];
    const float* Wq = (const float*)d_in[3];
    const float* bq = (const float*)d_in[4];
    const float* Wk = (const float*)d_in[5];
    const float* bk = (const float*)d_in[6];
    const float* Wv = (const float*)d_in[7];
    const float* bv = (const float*)d_in[8];
    const float* Wg = (const float*)d_in[9];
    const float* bg = (const float*)d_in[10];
    const float* Wo = (const float*)d_in[11];
    const float* bo = (const float*)d_in[12];
    float* out = (float*)d_out;

    float* gatep;
    cudaGetSymbolAddress((void**)&gatep, g_gate);

    bf16 *xqh,*xql,*xkh,*xkl,*xvh,*xvl,*hh,*hl;
    bf16 *wqh,*wql,*wkh,*wkl,*wvh,*wvl,*wgh,*wgl,*woh,*wol;
    bf16 *qh,*ql,*kh,*kl,*vh,*vl;
    cudaGetSymbolAddress((void**)&xqh, g_xqh); cudaGetSymbolAddress((void**)&xql, g_xql);
    cudaGetSymbolAddress((void**)&xkh, g_xkh); cudaGetSymbolAddress((void**)&xkl, g_xkl);
    cudaGetSymbolAddress((void**)&xvh, g_xvh); cudaGetSymbolAddress((void**)&xvl, g_xvl);
    cudaGetSymbolAddress((void**)&hh, g_hh);   cudaGetSymbolAddress((void**)&hl, g_hl);
    cudaGetSymbolAddress((void**)&wqh, g_wqh); cudaGetSymbolAddress((void**)&wql, g_wql);
    cudaGetSymbolAddress((void**)&wkh, g_wkh); cudaGetSymbolAddress((void**)&wkl, g_wkl);
    cudaGetSymbolAddress((void**)&wvh, g_wvh); cudaGetSymbolAddress((void**)&wvl, g_wvl);
    cudaGetSymbolAddress((void**)&wgh, g_wgh); cudaGetSymbolAddress((void**)&wgl, g_wgl);
    cudaGetSymbolAddress((void**)&woh, g_woh); cudaGetSymbolAddress((void**)&wol, g_wol);
    cudaGetSymbolAddress((void**)&qh, g_qh);   cudaGetSymbolAddress((void**)&ql, g_ql);
    cudaGetSymbolAddress((void**)&kh, g_kh);   cudaGetSymbolAddress((void**)&kl, g_kl);
    cudaGetSymbolAddress((void**)&vh, g_vh);   cudaGetSymbolAddress((void**)&vl, g_vl);

    cudaFuncSetAttribute(gemm_mma, cudaFuncAttributeMaxDynamicSharedMemorySize, GSMEM);
    cudaFuncSetAttribute(attention_mma, cudaFuncAttributeMaxDynamicSharedMemorySize, AT_SMEM);

    init_tables<<<256, 256>>>();

    const int NA4 = MROWS * EMB / 4;   // 1048576
    const int NW4 = EMB * EMB / 4;     // 262144
    ConvArgs ca;
    ca.j[0] = { (const float4*)query,  (uint2*)xqh, (uint2*)xql, NA4 };
    ca.j[1] = { (const float4*)key_in, (uint2*)xkh, (uint2*)xkl, NA4 };
    ca.j[2] = { (const float4*)value,  (uint2*)xvh, (uint2*)xvl, NA4 };
    ca.j[3] = { (const float4*)Wq, (uint2*)wqh, (uint2*)wql, NW4 };
    ca.j[4] = { (const float4*)Wk, (uint2*)wkh, (uint2*)wkl, NW4 };
    ca.j[5] = { (const float4*)Wv, (uint2*)wvh, (uint2*)wvl, NW4 };
    ca.j[6] = { (const float4*)Wg, (uint2*)wgh, (uint2*)wgl, NW4 };
    ca.j[7] = { (const float4*)Wo, (uint2*)woh, (uint2*)wol, NW4 };
    convert_all<<<dim3((NA4 + 255) / 256, 8), 256>>>(ca);

    // 4 projection GEMMs in ONE launch (1024 CTAs)
    GemmArgs pa;
    pa.j[0] = { xqh, xql, wqh, wql, bq, nullptr, qh, ql, 1 };
    pa.j[1] = { xkh, xkl, wkh, wkl, bk, nullptr, kh, kl, 2 };
    pa.j[2] = { xvh, xvl, wvh, wvl, bv, nullptr, vh, vl, 3 };
    pa.j[3] = { xqh, xql, wgh, wgl, bg, gatep, nullptr, nullptr, 4 };
    gemm_mma<<<dim3(EMB / 128, MROWS / 128, 4), 256, GSMEM>>>(pa);

    attention_mma<<<dim3(SEQ / 128, HEADS, BATCH), 256, AT_SMEM>>>();

    // final projection (depends on attention)
    GemmArgs fa;
    fa.j[0] = { hh, hl, woh, wol, bo, out, nullptr, nullptr, 0 };
    fa.j[1] = fa.j[0]; fa.j[2] = fa.j[0]; fa.j[3] = fa.j[0];
    gemm_mma<<<dim3(EMB / 128, MROWS / 128, 1), 256, GSMEM>>>(fa);
}